// round 6
// baseline (speedup 1.0000x reference)
#include <cuda_runtime.h>
#include <cuda_bf16.h>

#define NN 4096
#define DIN 512
#define DH1 256
#define DH2 64
#define ALPHA 0.2f

// packed fp32x2 helpers (used in zzt)
#define FMA2(d, a, b) asm("fma.rn.f32x2 %0, %1, %2, %0;" : "+l"(d) : "l"(a), "l"(b))
#define BPACK(d, s)   asm("mov.b64 %0, {%1, %1};" : "=l"(d) : "r"(__float_as_uint(s)))
#define UNPK(lo, hi, v) asm("mov.b64 {%0, %1}, %2;" : "=r"(lo), "=r"(hi) : "l"(v))

__device__ __forceinline__ void mma_tf32(float* c, const unsigned* a, unsigned b0, unsigned b1) {
    asm volatile("mma.sync.aligned.m16n8k8.row.col.f32.tf32.tf32.f32 "
                 "{%0,%1,%2,%3}, {%4,%5,%6,%7}, {%8,%9}, {%0,%1,%2,%3};"
                 : "+f"(c[0]), "+f"(c[1]), "+f"(c[2]), "+f"(c[3])
                 : "r"(a[0]), "r"(a[1]), "r"(a[2]), "r"(a[3]), "r"(b0), "r"(b1));
}

// ---------------- device scratch (no allocations allowed) ----------------
__device__ float    g_h0[NN * DH1];
__device__ float    g_hidden[NN * DH1];
__device__ float    g_h1[NN * DH2];
__device__ float    g_h2[NN * DH2];
__device__ float    g_mean[NN * DH2];
__device__ float    g_logstd[NN * DH2];
__device__ float    g_Z[NN * DH2];
__device__ float4   g_rowvals[NN];
__device__ float4   g_colvals[NN];
__device__ unsigned g_adjbits[NN * (NN / 32)];
__device__ float    g_pacc[8 * NN * DH1];   // 32 MB: holds 8*N*256 or 16*N*64
__device__ float    g_pden[16 * NN];

// ---------------- pack adjacency into bitmask (2 MB, L2-resident) --------
__global__ void pack_adj_kernel(const int* __restrict__ adj, unsigned* __restrict__ bits) {
    int idx = blockIdx.x * 256 + threadIdx.x;
    unsigned b = __ballot_sync(0xffffffffu, adj[idx] > 0);
    if ((threadIdx.x & 31) == 0) bits[idx >> 5] = b;
}

// ---------------- generic tiled fp32 GEMM: C[M,Nc] = A[M,K] @ B[K,Nc] ----
__global__ __launch_bounds__(256) void gemm64_kernel(
    const float* __restrict__ A, const float* __restrict__ B, float* __restrict__ C,
    int M, int K, int Nc)
{
    __shared__ float As[16][68];
    __shared__ float Bs[16][68];
    const int tid = threadIdx.x;
    const int tx = tid & 15, ty = tid >> 4;
    const int m0 = blockIdx.y * 64, n0 = blockIdx.x * 64;
    const int am = tid >> 2;
    const int ak = (tid & 3) * 4;
    const int bk = tid >> 4;
    const int bn = (tid & 15) * 4;

    float acc[4][4] = {};
    for (int k0 = 0; k0 < K; k0 += 16) {
        float4 av = *(const float4*)&A[(size_t)(m0 + am) * K + k0 + ak];
        float4 bv = *(const float4*)&B[(size_t)(k0 + bk) * Nc + n0 + bn];
        __syncthreads();
        As[ak + 0][am] = av.x; As[ak + 1][am] = av.y;
        As[ak + 2][am] = av.z; As[ak + 3][am] = av.w;
        *(float4*)&Bs[bk][bn] = bv;
        __syncthreads();
#pragma unroll
        for (int k = 0; k < 16; ++k) {
            float4 a4 = *(float4*)&As[k][ty * 4];
            float4 b4 = *(float4*)&Bs[k][tx * 4];
            acc[0][0] += a4.x * b4.x; acc[0][1] += a4.x * b4.y; acc[0][2] += a4.x * b4.z; acc[0][3] += a4.x * b4.w;
            acc[1][0] += a4.y * b4.x; acc[1][1] += a4.y * b4.y; acc[1][2] += a4.y * b4.z; acc[1][3] += a4.y * b4.w;
            acc[2][0] += a4.z * b4.x; acc[2][1] += a4.z * b4.y; acc[2][2] += a4.z * b4.z; acc[2][3] += a4.z * b4.w;
            acc[3][0] += a4.w * b4.x; acc[3][1] += a4.w * b4.y; acc[3][2] += a4.w * b4.z; acc[3][3] += a4.w * b4.w;
        }
    }
#pragma unroll
    for (int i = 0; i < 4; ++i) {
        float4 v = make_float4(acc[i][0], acc[i][1], acc[i][2], acc[i][3]);
        *(float4*)&C[(size_t)(m0 + ty * 4 + i) * Nc + n0 + tx * 4] = v;
    }
}

// ---------------- per-row attention scalars ------------------------------
__global__ void vals_kernel(const float* __restrict__ h, const float* __restrict__ a,
                            int D, float4* __restrict__ rowvals, float4* __restrict__ colvals)
{
    int warp = (blockIdx.x * blockDim.x + threadIdx.x) >> 5;
    int lane = threadIdx.x & 31;
    if (warp >= NN) return;
    float s1 = 0.f, s2 = 0.f;
    for (int d = lane; d < D; d += 32) {
        float hv = h[(size_t)warp * D + d];
        s1 += hv * a[d];
        s2 += hv * a[D + d];
    }
#pragma unroll
    for (int o = 16; o; o >>= 1) {
        s1 += __shfl_xor_sync(0xffffffffu, s1, o);
        s2 += __shfl_xor_sync(0xffffffffu, s2, o);
    }
    if (lane == 0) {
        rowvals[warp] = make_float4(-s1, expf(s1), expf(ALPHA * s1), 0.f);
        colvals[warp] = make_float4(s2, expf(s2), expf(ALPHA * s2), 0.f);
    }
}

// ---------------- attention v5: double-buffered pipelined tf32 mma -------
// Phase A writes weights directly into mma-fragment-swizzled layout (WsF).
// B operand stored as interleaved (k, k+4) pairs -> one LDS.64 per fragment.
// Per tile: LDG->regs issued, phase B (mma) overlaps latency, STS, phase A.
template<int D, int DC>
__global__ __launch_bounds__(256, 2) void attn5_kernel(
    const float* __restrict__ h,
    const float4* __restrict__ rowvals,
    const float4* __restrict__ colvals,
    const unsigned* __restrict__ adjbits,
    float* __restrict__ pacc,
    float* __restrict__ pden)
{
    constexpr int BI = 128, BJ = 32, FRAG = 132;
    constexpr int NT = DC / 16;            // COLG=2
    constexpr int DCpad = DC + 4;          // 132 / 68 (bank-clean for LDS.64)
    constexpr int WSF1 = 32 * FRAG;        // 4224 words per buffer
    constexpr int HSF1 = 16 * DCpad * 2;   // paired-B words per buffer
    constexpr int LD_IT = BJ * DC / (4 * 256);

    extern __shared__ __align__(16) unsigned smem_u[];
    unsigned* WsF = smem_u;                              // [2][WSF1]
    float*    hsF = (float*)(smem_u + 2 * WSF1);         // [2][HSF1]
    float4*   cvs = (float4*)(smem_u + 2 * WSF1 + 2 * HSF1);  // [2][32]
    float*    dpar = (float*)(smem_u + 2 * WSF1 + 2 * HSF1 + 256);

    const int tid = threadIdx.x;
    const int wid = tid >> 5, lane = tid & 31;
    const int grp = lane >> 2, tid4 = lane & 3;
    const int warpRow = wid & 3, warpCol = wid >> 2;
    const int rowbase = blockIdx.x * BI;
    const int colbase = blockIdx.y * DC;
    const int split = blockIdx.z;
    const int jcnt = NN / gridDim.z;
    const int jbeg = split * jcnt;
    const int T = jcnt / BJ;

    // phase-A per-thread constants (thread handles row iA, j-half jhalf)
    const int iA = tid & 127;
    const int jhalf = tid >> 7;
    const float4 rv = rowvals[rowbase + iA];   // (-f1, P, Q, _)
    const int mb = iA >> 4, ii = iA & 15;
    const int baseA = mb * FRAG + (ii & 7) * 16 + (ii >> 3) + jhalf * 16 * FRAG;
    float den = 0.f;

    float acc[2][NT][4];
#pragma unroll
    for (int m = 0; m < 2; ++m)
#pragma unroll
        for (int n = 0; n < NT; ++n)
#pragma unroll
            for (int q = 0; q < 4; ++q) acc[m][n][q] = 0.f;

    auto ldg_tile = [&](int t, float4* v, float4& c4, unsigned& mw) {
        const int j0 = jbeg + t * BJ;
#pragma unroll
        for (int it = 0; it < LD_IT; ++it) {
            int q = tid + it * 256;
            int row = q / (DC / 4);
            int n = (q % (DC / 4)) * 4;
            v[it] = *(const float4*)&h[(size_t)(j0 + row) * D + colbase + n];
        }
        if (tid < 32) c4 = colvals[j0 + tid];
        mw = adjbits[(size_t)(rowbase + iA) * (NN / 32) + (j0 >> 5)];
    };
    auto sts_tile = [&](int buf, const float4* v, const float4& c4) {
        float* hb = hsF + buf * HSF1;
#pragma unroll
        for (int it = 0; it < LD_IT; ++it) {
            int q = tid + it * 256;
            int row = q / (DC / 4);
            int n = (q % (DC / 4)) * 4;
            int rIdx = (row >> 3) * 4 + (row & 3);
            int s = (row >> 2) & 1;
            float* p = hb + (rIdx * DCpad + n) * 2 + s;
            p[0] = v[it].x; p[2] = v[it].y; p[4] = v[it].z; p[6] = v[it].w;
        }
        if (tid < 32) cvs[buf * 32 + tid] = c4;
    };
    auto phaseA = [&](int buf, unsigned mw) {
        unsigned* Wb = WsF + buf * WSF1;
        const float4* cv = cvs + buf * 32 + jhalf * 16;
        const unsigned msk = mw >> (jhalf * 16);
#pragma unroll
        for (int e = 0; e < 16; ++e) {
            float4 c = cv[e];
            bool p = c.x > rv.x;
            float w = p ? (rv.y * c.y) : (rv.z * c.z);
            w = ((msk >> e) & 1u) ? w : 0.f;
            den += w;
            int idx = baseA + (e >> 3) * (8 * FRAG) + (e & 3) * 4 + (((e >> 2) & 1) << 1);
            Wb[idx] = __float_as_uint(w);
        }
    };
    auto phaseB = [&](int buf) {
        unsigned* Wb = WsF + buf * WSF1;
        const float* hb = hsF + buf * HSF1;
#pragma unroll
        for (int kb = 0; kb < 4; ++kb) {
            uint4 af0 = *(const uint4*)&Wb[(kb * 8 + warpRow * 2 + 0) * FRAG + lane * 4];
            uint4 af1 = *(const uint4*)&Wb[(kb * 8 + warpRow * 2 + 1) * FRAG + lane * 4];
            const float* hrow = hb + (kb * 4 + tid4) * DCpad * 2;
#pragma unroll
            for (int n = 0; n < NT; ++n) {
                int nn = warpCol * (NT * 8) + n * 8 + grp;
                float2 bb = *(const float2*)&hrow[nn * 2];
                unsigned b0 = __float_as_uint(bb.x), b1 = __float_as_uint(bb.y);
                mma_tf32(acc[0][n], (const unsigned*)&af0, b0, b1);
                mma_tf32(acc[1][n], (const unsigned*)&af1, b0, b1);
            }
        }
    };

    // prologue: tile 0
    {
        float4 v[LD_IT]; float4 c4; unsigned mw;
        ldg_tile(0, v, c4, mw);
        sts_tile(0, v, c4);
        __syncthreads();
        phaseA(0, mw);
    }

    for (int t = 0; t < T; ++t) {
        const int cur = t & 1, nxt = cur ^ 1;
        __syncthreads();                       // WsF[cur] complete
        float4 v[LD_IT]; float4 c4; unsigned mw = 0;
        const bool more = (t + 1 < T);
        if (more) ldg_tile(t + 1, v, c4, mw);  // LDG in flight during phase B
        phaseB(cur);
        if (more) sts_tile(nxt, v, c4);
        __syncthreads();                       // hs/cvs[nxt] visible
        if (more) phaseA(nxt, mw);
    }

    // epilogue: write partial accumulators + denominators
#pragma unroll
    for (int m = 0; m < 2; ++m) {
        int r0 = rowbase + (warpRow * 2 + m) * 16 + grp;
#pragma unroll
        for (int n = 0; n < NT; ++n) {
            int col = colbase + warpCol * (NT * 8) + n * 8 + 2 * tid4;
            float* p0 = pacc + ((size_t)split * NN + r0) * D + col;
            float* p1 = pacc + ((size_t)split * NN + r0 + 8) * D + col;
            *(float2*)p0 = make_float2(acc[m][n][0], acc[m][n][1]);
            *(float2*)p1 = make_float2(acc[m][n][2], acc[m][n][3]);
        }
    }
    dpar[tid] = den;
    __syncthreads();
    if (blockIdx.y == 0 && tid < BI)
        pden[split * NN + rowbase + tid] = dpar[tid] + dpar[tid + 128];
}

// ---------------- combine split partials + normalize ---------------------
__global__ void combine_kernel(const float* __restrict__ pacc, const float* __restrict__ pden,
                               float* __restrict__ out, int D, int nsplit)
{
    int idx = blockIdx.x * blockDim.x + threadIdx.x;
    int total = NN * D / 4;
    if (idx >= total) return;
    int row = idx / (D / 4);
    float4 s = make_float4(0.f, 0.f, 0.f, 0.f);
    float dd = 0.f;
    for (int sp = 0; sp < nsplit; ++sp) {
        float4 v = ((const float4*)pacc)[(size_t)sp * total + idx];
        s.x += v.x; s.y += v.y; s.z += v.z; s.w += v.w;
        dd += pden[sp * NN + row];
    }
    float inv = 1.f / dd;
    s.x *= inv; s.y *= inv; s.z *= inv; s.w *= inv;
    ((float4*)out)[idx] = s;
}

// ---------------- Z = noise * exp(logstd) + mean -------------------------
__global__ void z_kernel(const float* __restrict__ noise, const float* __restrict__ logstd,
                         const float* __restrict__ mean, float* __restrict__ Z)
{
    int idx = blockIdx.x * blockDim.x + threadIdx.x;
    if (idx >= NN * DH2) return;
    Z[idx] = noise[idx] * expf(logstd[idx]) + mean[idx];
}

// ---------------- A = sigmoid(Z @ Z^T), symmetric, FFMA2 -----------------
__global__ __launch_bounds__(256) void zzt_kernel(const float* __restrict__ Z, float* __restrict__ out)
{
    const int bi = blockIdx.y, bj = blockIdx.x;
    if (bj < bi) return;
    __shared__ __align__(16) float ZiT[64][68];
    __shared__ __align__(16) float ZjT[64][68];
    const int tid = threadIdx.x;
    const int r = tid >> 2;
    const int kq = (tid & 3) * 16;
    const int i0 = bi * 64, j0 = bj * 64;
#pragma unroll
    for (int q = 0; q < 4; ++q) {
        int k = kq + q * 4;
        float4 v = *(const float4*)&Z[(size_t)(i0 + r) * DH2 + k];
        ZiT[k + 0][r] = v.x; ZiT[k + 1][r] = v.y; ZiT[k + 2][r] = v.z; ZiT[k + 3][r] = v.w;
        float4 u = *(const float4*)&Z[(size_t)(j0 + r) * DH2 + k];
        ZjT[k + 0][r] = u.x; ZjT[k + 1][r] = u.y; ZjT[k + 2][r] = u.z; ZjT[k + 3][r] = u.w;
    }
    __syncthreads();
    const int tx = tid & 15, ty = tid >> 4;
    unsigned long long acc2[4][2];
#pragma unroll
    for (int i = 0; i < 4; ++i) { acc2[i][0] = 0ULL; acc2[i][1] = 0ULL; }
#pragma unroll 16
    for (int k = 0; k < 64; ++k) {
        float4 a4 = *(float4*)&ZiT[k][ty * 4];
        ulonglong2 b2 = *(ulonglong2*)&ZjT[k][tx * 4];
        unsigned long long ap[4];
        BPACK(ap[0], a4.x); BPACK(ap[1], a4.y); BPACK(ap[2], a4.z); BPACK(ap[3], a4.w);
#pragma unroll
        for (int i = 0; i < 4; ++i) {
            FMA2(acc2[i][0], ap[i], b2.x);
            FMA2(acc2[i][1], ap[i], b2.y);
        }
    }
    float s[4][4];
#pragma unroll
    for (int i = 0; i < 4; ++i) {
        unsigned l0, h0, l1, h1;
        UNPK(l0, h0, acc2[i][0]);
        UNPK(l1, h1, acc2[i][1]);
        s[i][0] = __fdividef(1.f, 1.f + __expf(-__uint_as_float(l0)));
        s[i][1] = __fdividef(1.f, 1.f + __expf(-__uint_as_float(h0)));
        s[i][2] = __fdividef(1.f, 1.f + __expf(-__uint_as_float(l1)));
        s[i][3] = __fdividef(1.f, 1.f + __expf(-__uint_as_float(h1)));
    }
#pragma unroll
    for (int i = 0; i < 4; ++i) {
        float4 v = make_float4(s[i][0], s[i][1], s[i][2], s[i][3]);
        *(float4*)&out[(size_t)(i0 + ty * 4 + i) * NN + j0 + tx * 4] = v;
    }
    if (bj > bi) {
#pragma unroll
        for (int j = 0; j < 4; ++j) {
            float4 v = make_float4(s[0][j], s[1][j], s[2][j], s[3][j]);
            *(float4*)&out[(size_t)(j0 + tx * 4 + j) * NN + i0 + ty * 4] = v;
        }
    }
}

// ---------------- host orchestration -------------------------------------
extern "C" void kernel_launch(void* const* d_in, const int* in_sizes, int n_in,
                              void* d_out, int out_size)
{
    const float* X     = (const float*)d_in[0];
    const int*   adj   = (const int*)  d_in[1];
    const float* noise = (const float*)d_in[2];
    const float* W0    = (const float*)d_in[3];
    const float* a0    = (const float*)d_in[4];
    const float* W1    = (const float*)d_in[5];
    const float* a1    = (const float*)d_in[6];
    const float* W2    = (const float*)d_in[7];
    const float* a2    = (const float*)d_in[8];
    float* out = (float*)d_out;

    float *p_h0, *p_hidden, *p_h1, *p_h2, *p_mean, *p_logstd, *p_Z, *p_pacc, *p_pden;
    float4 *p_rv, *p_cv;
    unsigned* p_bits;
    cudaGetSymbolAddress((void**)&p_h0, g_h0);
    cudaGetSymbolAddress((void**)&p_hidden, g_hidden);
    cudaGetSymbolAddress((void**)&p_h1, g_h1);
    cudaGetSymbolAddress((void**)&p_h2, g_h2);
    cudaGetSymbolAddress((void**)&p_mean, g_mean);
    cudaGetSymbolAddress((void**)&p_logstd, g_logstd);
    cudaGetSymbolAddress((void**)&p_Z, g_Z);
    cudaGetSymbolAddress((void**)&p_pacc, g_pacc);
    cudaGetSymbolAddress((void**)&p_pden, g_pden);
    cudaGetSymbolAddress((void**)&p_rv, g_rowvals);
    cudaGetSymbolAddress((void**)&p_cv, g_colvals);
    cudaGetSymbolAddress((void**)&p_bits, g_adjbits);

    const int smem256 = (2 * 32 * 132 + 2 * 16 * 132 * 2 + 512) * 4;  // 69632
    const int smem64  = (2 * 32 * 132 + 2 * 16 * 68 * 2 + 512) * 4;   // 53248
    cudaFuncSetAttribute(attn5_kernel<DH1, 128>, cudaFuncAttributeMaxDynamicSharedMemorySize, smem256);
    cudaFuncSetAttribute(attn5_kernel<DH2, 64>,  cudaFuncAttributeMaxDynamicSharedMemorySize, smem64);

    // adjacency bitmask
    pack_adj_kernel<<<NN * NN / 256, 256>>>(adj, p_bits);

    // ---- layer 0: h0 = X@W0 ; hidden = attn(h0) ----
    gemm64_kernel<<<dim3(DH1 / 64, NN / 64), 256>>>(X, W0, p_h0, NN, DIN, DH1);
    vals_kernel<<<NN / 8, 256>>>(p_h0, a0, DH1, p_rv, p_cv);
    attn5_kernel<DH1, 128><<<dim3(NN / 128, 2, 8), 256, smem256>>>(p_h0, p_rv, p_cv, p_bits, p_pacc, p_pden);
    combine_kernel<<<NN * DH1 / 4 / 256, 256>>>(p_pacc, p_pden, p_hidden, DH1, 8);

    // ---- layer 1 (mean) ----
    gemm64_kernel<<<dim3(DH2 / 64, NN / 64), 256>>>(p_hidden, W1, p_h1, NN, DH1, DH2);
    vals_kernel<<<NN / 8, 256>>>(p_h1, a1, DH2, p_rv, p_cv);
    attn5_kernel<DH2, 64><<<dim3(NN / 128, 1, 16), 256, smem64>>>(p_h1, p_rv, p_cv, p_bits, p_pacc, p_pden);
    combine_kernel<<<NN * DH2 / 4 / 256, 256>>>(p_pacc, p_pden, p_mean, DH2, 16);

    // ---- layer 2 (logstd) ----
    gemm64_kernel<<<dim3(DH2 / 64, NN / 64), 256>>>(p_hidden, W2, p_h2, NN, DH1, DH2);
    vals_kernel<<<NN / 8, 256>>>(p_h2, a2, DH2, p_rv, p_cv);
    attn5_kernel<DH2, 64><<<dim3(NN / 128, 1, 16), 256, smem64>>>(p_h2, p_rv, p_cv, p_bits, p_pacc, p_pden);
    combine_kernel<<<NN * DH2 / 4 / 256, 256>>>(p_pacc, p_pden, p_logstd, DH2, 16);

    // ---- Z and decoder ----
    z_kernel<<<NN * DH2 / 256, 256>>>(noise, p_logstd, p_mean, p_Z);
    zzt_kernel<<<dim3(NN / 64, NN / 64), 256>>>(p_Z, out);
}

// round 7
// speedup vs baseline: 1.1111x; 1.1111x over previous
#include <cuda_runtime.h>
#include <cuda_bf16.h>

#define NN 4096
#define DIN 512
#define DH1 256
#define DH2 64
#define ALPHA 0.2f

// packed fp32x2 helpers (used in zzt)
#define FMA2(d, a, b) asm("fma.rn.f32x2 %0, %1, %2, %0;" : "+l"(d) : "l"(a), "l"(b))
#define BPACK(d, s)   asm("mov.b64 %0, {%1, %1};" : "=l"(d) : "r"(__float_as_uint(s)))
#define UNPK(lo, hi, v) asm("mov.b64 {%0, %1}, %2;" : "=r"(lo), "=r"(hi) : "l"(v))

__device__ __forceinline__ unsigned f2tf(float f) {
    unsigned u; asm("cvt.rna.tf32.f32 %0, %1;" : "=r"(u) : "f"(f)); return u;
}
__device__ __forceinline__ void mma_tf32(float* c, const unsigned* a, unsigned b0, unsigned b1) {
    asm volatile("mma.sync.aligned.m16n8k8.row.col.f32.tf32.tf32.f32 "
                 "{%0,%1,%2,%3}, {%4,%5,%6,%7}, {%8,%9}, {%0,%1,%2,%3};"
                 : "+f"(c[0]), "+f"(c[1]), "+f"(c[2]), "+f"(c[3])
                 : "r"(a[0]), "r"(a[1]), "r"(a[2]), "r"(a[3]), "r"(b0), "r"(b1));
}

// ---------------- device scratch (no allocations allowed) ----------------
__device__ float    g_h0[NN * DH1];
__device__ float    g_hidden[NN * DH1];
__device__ float    g_h1[NN * DH2];
__device__ float    g_h2[NN * DH2];
__device__ float    g_mean[NN * DH2];
__device__ float    g_logstd[NN * DH2];
__device__ float    g_Z[NN * DH2];
__device__ float4   g_rowvals[NN];
__device__ float4   g_colvals[NN];
__device__ unsigned g_adjbits[NN * (NN / 32)];
__device__ float    g_pacc[8 * NN * DH1];
__device__ float    g_pden[16 * NN];

// ---------------- pack adjacency into bitmask (2 MB, L2-resident) --------
__global__ void pack_adj_kernel(const int* __restrict__ adj, unsigned* __restrict__ bits) {
    int idx = blockIdx.x * 256 + threadIdx.x;
    unsigned b = __ballot_sync(0xffffffffu, adj[idx] > 0);
    if ((threadIdx.x & 31) == 0) bits[idx >> 5] = b;
}

// ---------------- generic tiled fp32 GEMM: C[M,Nc] = A[M,K] @ B[K,Nc] ----
__global__ __launch_bounds__(256) void gemm64_kernel(
    const float* __restrict__ A, const float* __restrict__ B, float* __restrict__ C,
    int M, int K, int Nc)
{
    __shared__ float As[16][68];
    __shared__ float Bs[16][68];
    const int tid = threadIdx.x;
    const int tx = tid & 15, ty = tid >> 4;
    const int m0 = blockIdx.y * 64, n0 = blockIdx.x * 64;
    const int am = tid >> 2;
    const int ak = (tid & 3) * 4;
    const int bk = tid >> 4;
    const int bn = (tid & 15) * 4;

    float acc[4][4] = {};
    for (int k0 = 0; k0 < K; k0 += 16) {
        float4 av = *(const float4*)&A[(size_t)(m0 + am) * K + k0 + ak];
        float4 bv = *(const float4*)&B[(size_t)(k0 + bk) * Nc + n0 + bn];
        __syncthreads();
        As[ak + 0][am] = av.x; As[ak + 1][am] = av.y;
        As[ak + 2][am] = av.z; As[ak + 3][am] = av.w;
        *(float4*)&Bs[bk][bn] = bv;
        __syncthreads();
#pragma unroll
        for (int k = 0; k < 16; ++k) {
            float4 a4 = *(float4*)&As[k][ty * 4];
            float4 b4 = *(float4*)&Bs[k][tx * 4];
            acc[0][0] += a4.x * b4.x; acc[0][1] += a4.x * b4.y; acc[0][2] += a4.x * b4.z; acc[0][3] += a4.x * b4.w;
            acc[1][0] += a4.y * b4.x; acc[1][1] += a4.y * b4.y; acc[1][2] += a4.y * b4.z; acc[1][3] += a4.y * b4.w;
            acc[2][0] += a4.z * b4.x; acc[2][1] += a4.z * b4.y; acc[2][2] += a4.z * b4.z; acc[2][3] += a4.z * b4.w;
            acc[3][0] += a4.w * b4.x; acc[3][1] += a4.w * b4.y; acc[3][2] += a4.w * b4.z; acc[3][3] += a4.w * b4.w;
        }
    }
#pragma unroll
    for (int i = 0; i < 4; ++i) {
        float4 v = make_float4(acc[i][0], acc[i][1], acc[i][2], acc[i][3]);
        *(float4*)&C[(size_t)(m0 + ty * 4 + i) * Nc + n0 + tx * 4] = v;
    }
}

// ---------------- per-row attention scalars ------------------------------
__global__ void vals_kernel(const float* __restrict__ h, const float* __restrict__ a,
                            int D, float4* __restrict__ rowvals, float4* __restrict__ colvals)
{
    int warp = (blockIdx.x * blockDim.x + threadIdx.x) >> 5;
    int lane = threadIdx.x & 31;
    if (warp >= NN) return;
    float s1 = 0.f, s2 = 0.f;
    for (int d = lane; d < D; d += 32) {
        float hv = h[(size_t)warp * D + d];
        s1 += hv * a[d];
        s2 += hv * a[D + d];
    }
#pragma unroll
    for (int o = 16; o; o >>= 1) {
        s1 += __shfl_xor_sync(0xffffffffu, s1, o);
        s2 += __shfl_xor_sync(0xffffffffu, s2, o);
    }
    if (lane == 0) {
        rowvals[warp] = make_float4(-s1, expf(s1), expf(ALPHA * s1), 0.f);
        colvals[warp] = make_float4(s2, expf(s2), expf(ALPHA * s2), 0.f);
    }
}

// ---------------- attention v6: attn3 layouts + double-buffered pipeline --
// Phase A: W[32][BIp] tile (cvt.rna tf32) + register denominators.
// Phase B: tf32 mma GEMM (conflict-free padded layouts, as attn3).
// Schedule: LDG(t+1)->regs | mma(t) | STS(t+1) | sync | phaseA(t+1) | sync.
template<int D, int DC, int MT, int ROWG, int COLG>
__global__ __launch_bounds__(256, 2) void attn6_kernel(
    const float* __restrict__ h,
    const float4* __restrict__ rowvals,
    const float4* __restrict__ colvals,
    const unsigned* __restrict__ adjbits,
    float* __restrict__ pacc,
    float* __restrict__ pden)
{
    constexpr int BI = 128, BJ = 32, BIp = 136;
    constexpr int DCp = DC + 8;
    constexpr int NT = DC / COLG / 8;
    constexpr int WSF1 = BJ * BIp;
    constexpr int HSF1 = BJ * DCp;
    constexpr int LD_IT = BJ * DC / (4 * 256);

    extern __shared__ __align__(16) unsigned smem_u[];
    unsigned* Ws = smem_u;                                    // [2][WSF1]
    unsigned* hs = smem_u + 2 * WSF1;                         // [2][HSF1]
    float4*   cvs = (float4*)(smem_u + 2 * WSF1 + 2 * HSF1);  // [2][32]
    float*    dpar = (float*)(smem_u + 2 * WSF1 + 2 * HSF1 + 256);

    const int tid = threadIdx.x;
    const int wid = tid >> 5, lane = tid & 31;
    const int grp = lane >> 2, tid4 = lane & 3;
    const int warpRow = wid % ROWG, warpCol = wid / ROWG;
    const int rowbase = blockIdx.x * BI;
    const int colbase = blockIdx.y * DC;
    const int split = blockIdx.z;
    const int jcnt = NN / gridDim.z;
    const int jbeg = split * jcnt;
    const int T = jcnt / BJ;

    const int iA = tid & 127;
    const int jAb = (tid >> 7) * 16;
    const float4 rv = rowvals[rowbase + iA];   // (-f1, P, Q, _)
    float den = 0.f;

    float acc[MT][NT][4];
#pragma unroll
    for (int m = 0; m < MT; ++m)
#pragma unroll
        for (int n = 0; n < NT; ++n)
#pragma unroll
            for (int q = 0; q < 4; ++q) acc[m][n][q] = 0.f;

    auto ldg_tile = [&](int t, float4* v, float4& c4, unsigned& mw) {
        const int j0 = jbeg + t * BJ;
#pragma unroll
        for (int it = 0; it < LD_IT; ++it) {
            int q = tid + it * 256;
            int row = q / (DC / 4);
            int c = (q % (DC / 4)) * 4;
            v[it] = *(const float4*)&h[(size_t)(j0 + row) * D + colbase + c];
        }
        if (tid < 32) c4 = colvals[j0 + tid];
        mw = adjbits[(size_t)(rowbase + iA) * (NN / 32) + (j0 >> 5)];
    };
    auto sts_tile = [&](int buf, const float4* v, const float4& c4) {
        unsigned* hb = hs + buf * HSF1;
#pragma unroll
        for (int it = 0; it < LD_IT; ++it) {
            int q = tid + it * 256;
            int row = q / (DC / 4);
            int c = (q % (DC / 4)) * 4;
            uint4 t4;
            t4.x = f2tf(v[it].x); t4.y = f2tf(v[it].y);
            t4.z = f2tf(v[it].z); t4.w = f2tf(v[it].w);
            *(uint4*)&hb[row * DCp + c] = t4;
        }
        if (tid < 32) cvs[buf * 32 + tid] = c4;
    };
    auto phaseA = [&](int buf, unsigned mw) {
        unsigned* Wb = Ws + buf * WSF1;
        const float4* cv = cvs + buf * 32;
        const unsigned msk = mw >> jAb;
#pragma unroll
        for (int e = 0; e < 16; ++e) {
            int j = jAb + e;
            float4 c = cv[j];
            bool p = c.x > rv.x;
            float w = p ? (rv.y * c.y) : (rv.z * c.z);
            w = ((msk >> e) & 1u) ? w : 0.f;
            den += w;
            Wb[j * BIp + iA] = f2tf(w);
        }
    };
    auto phaseB = [&](int buf) {
        const unsigned* Wb = Ws + buf * WSF1;
        const unsigned* hb = hs + buf * HSF1;
#pragma unroll
        for (int k0 = 0; k0 < BJ; k0 += 8) {
            unsigned afr[MT][4];
#pragma unroll
            for (int m = 0; m < MT; ++m) {
                int rb = (warpRow * MT + m) * 16;
                afr[m][0] = Wb[(k0 + tid4) * BIp + rb + grp];
                afr[m][1] = Wb[(k0 + tid4) * BIp + rb + grp + 8];
                afr[m][2] = Wb[(k0 + tid4 + 4) * BIp + rb + grp];
                afr[m][3] = Wb[(k0 + tid4 + 4) * BIp + rb + grp + 8];
            }
#pragma unroll
            for (int n = 0; n < NT; ++n) {
                int n0 = warpCol * (NT * 8) + n * 8;
                unsigned b0 = hb[(k0 + tid4) * DCp + n0 + grp];
                unsigned b1 = hb[(k0 + tid4 + 4) * DCp + n0 + grp];
#pragma unroll
                for (int m = 0; m < MT; ++m)
                    mma_tf32(acc[m][n], afr[m], b0, b1);
            }
        }
    };

    // prologue: tile 0
    {
        float4 v[LD_IT]; float4 c4 = make_float4(0, 0, 0, 0); unsigned mw;
        ldg_tile(0, v, c4, mw);
        sts_tile(0, v, c4);
        __syncthreads();
        phaseA(0, mw);
    }

    for (int t = 0; t < T; ++t) {
        const int cur = t & 1, nxt = cur ^ 1;
        __syncthreads();                       // Ws[cur] complete
        float4 v[LD_IT]; float4 c4 = make_float4(0, 0, 0, 0); unsigned mw = 0;
        const bool more = (t + 1 < T);
        if (more) ldg_tile(t + 1, v, c4, mw);  // LDG in flight during mma
        phaseB(cur);
        if (more) sts_tile(nxt, v, c4);
        __syncthreads();                       // hs/cvs[nxt] visible
        if (more) phaseA(nxt, mw);
    }

    // epilogue
#pragma unroll
    for (int m = 0; m < MT; ++m) {
        int r0 = rowbase + (warpRow * MT + m) * 16 + grp;
#pragma unroll
        for (int n = 0; n < NT; ++n) {
            int col = colbase + warpCol * (NT * 8) + n * 8 + 2 * tid4;
            float* p0 = pacc + ((size_t)split * NN + r0) * D + col;
            float* p1 = pacc + ((size_t)split * NN + r0 + 8) * D + col;
            *(float2*)p0 = make_float2(acc[m][n][0], acc[m][n][1]);
            *(float2*)p1 = make_float2(acc[m][n][2], acc[m][n][3]);
        }
    }
    dpar[tid] = den;
    __syncthreads();
    if (blockIdx.y == 0 && tid < BI)
        pden[split * NN + rowbase + tid] = dpar[tid] + dpar[tid + 128];
}

// ---------------- combine split partials + normalize ---------------------
__global__ void combine_kernel(const float* __restrict__ pacc, const float* __restrict__ pden,
                               float* __restrict__ out, int D, int nsplit)
{
    int idx = blockIdx.x * blockDim.x + threadIdx.x;
    int total = NN * D / 4;
    if (idx >= total) return;
    int row = idx / (D / 4);
    float4 s = make_float4(0.f, 0.f, 0.f, 0.f);
    float dd = 0.f;
    for (int sp = 0; sp < nsplit; ++sp) {
        float4 v = ((const float4*)pacc)[(size_t)sp * total + idx];
        s.x += v.x; s.y += v.y; s.z += v.z; s.w += v.w;
        dd += pden[sp * NN + row];
    }
    float inv = 1.f / dd;
    s.x *= inv; s.y *= inv; s.z *= inv; s.w *= inv;
    ((float4*)out)[idx] = s;
}

// ---------------- Z = noise * exp(logstd) + mean -------------------------
__global__ void z_kernel(const float* __restrict__ noise, const float* __restrict__ logstd,
                         const float* __restrict__ mean, float* __restrict__ Z)
{
    int idx = blockIdx.x * blockDim.x + threadIdx.x;
    if (idx >= NN * DH2) return;
    Z[idx] = noise[idx] * expf(logstd[idx]) + mean[idx];
}

// ---------------- A = sigmoid(Z @ Z^T), symmetric, FFMA2 -----------------
__global__ __launch_bounds__(256) void zzt_kernel(const float* __restrict__ Z, float* __restrict__ out)
{
    const int bi = blockIdx.y, bj = blockIdx.x;
    if (bj < bi) return;
    __shared__ __align__(16) float ZiT[64][68];
    __shared__ __align__(16) float ZjT[64][68];
    const int tid = threadIdx.x;
    const int r = tid >> 2;
    const int kq = (tid & 3) * 16;
    const int i0 = bi * 64, j0 = bj * 64;
#pragma unroll
    for (int q = 0; q < 4; ++q) {
        int k = kq + q * 4;
        float4 v = *(const float4*)&Z[(size_t)(i0 + r) * DH2 + k];
        ZiT[k + 0][r] = v.x; ZiT[k + 1][r] = v.y; ZiT[k + 2][r] = v.z; ZiT[k + 3][r] = v.w;
        float4 u = *(const float4*)&Z[(size_t)(j0 + r) * DH2 + k];
        ZjT[k + 0][r] = u.x; ZjT[k + 1][r] = u.y; ZjT[k + 2][r] = u.z; ZjT[k + 3][r] = u.w;
    }
    __syncthreads();
    const int tx = tid & 15, ty = tid >> 4;
    unsigned long long acc2[4][2];
#pragma unroll
    for (int i = 0; i < 4; ++i) { acc2[i][0] = 0ULL; acc2[i][1] = 0ULL; }
#pragma unroll 16
    for (int k = 0; k < 64; ++k) {
        float4 a4 = *(float4*)&ZiT[k][ty * 4];
        ulonglong2 b2 = *(ulonglong2*)&ZjT[k][tx * 4];
        unsigned long long ap[4];
        BPACK(ap[0], a4.x); BPACK(ap[1], a4.y); BPACK(ap[2], a4.z); BPACK(ap[3], a4.w);
#pragma unroll
        for (int i = 0; i < 4; ++i) {
            FMA2(acc2[i][0], ap[i], b2.x);
            FMA2(acc2[i][1], ap[i], b2.y);
        }
    }
    float s[4][4];
#pragma unroll
    for (int i = 0; i < 4; ++i) {
        unsigned l0, h0, l1, h1;
        UNPK(l0, h0, acc2[i][0]);
        UNPK(l1, h1, acc2[i][1]);
        s[i][0] = __fdividef(1.f, 1.f + __expf(-__uint_as_float(l0)));
        s[i][1] = __fdividef(1.f, 1.f + __expf(-__uint_as_float(h0)));
        s[i][2] = __fdividef(1.f, 1.f + __expf(-__uint_as_float(l1)));
        s[i][3] = __fdividef(1.f, 1.f + __expf(-__uint_as_float(h1)));
    }
#pragma unroll
    for (int i = 0; i < 4; ++i) {
        float4 v = make_float4(s[i][0], s[i][1], s[i][2], s[i][3]);
        *(float4*)&out[(size_t)(i0 + ty * 4 + i) * NN + j0 + tx * 4] = v;
    }
    if (bj > bi) {
#pragma unroll
        for (int j = 0; j < 4; ++j) {
            float4 v = make_float4(s[0][j], s[1][j], s[2][j], s[3][j]);
            *(float4*)&out[(size_t)(j0 + tx * 4 + j) * NN + i0 + ty * 4] = v;
        }
    }
}

// ---------------- host orchestration -------------------------------------
extern "C" void kernel_launch(void* const* d_in, const int* in_sizes, int n_in,
                              void* d_out, int out_size)
{
    const float* X     = (const float*)d_in[0];
    const int*   adj   = (const int*)  d_in[1];
    const float* noise = (const float*)d_in[2];
    const float* W0    = (const float*)d_in[3];
    const float* a0    = (const float*)d_in[4];
    const float* W1    = (const float*)d_in[5];
    const float* a1    = (const float*)d_in[6];
    const float* W2    = (const float*)d_in[7];
    const float* a2    = (const float*)d_in[8];
    float* out = (float*)d_out;

    float *p_h0, *p_hidden, *p_h1, *p_h2, *p_mean, *p_logstd, *p_Z, *p_pacc, *p_pden;
    float4 *p_rv, *p_cv;
    unsigned* p_bits;
    cudaGetSymbolAddress((void**)&p_h0, g_h0);
    cudaGetSymbolAddress((void**)&p_hidden, g_hidden);
    cudaGetSymbolAddress((void**)&p_h1, g_h1);
    cudaGetSymbolAddress((void**)&p_h2, g_h2);
    cudaGetSymbolAddress((void**)&p_mean, g_mean);
    cudaGetSymbolAddress((void**)&p_logstd, g_logstd);
    cudaGetSymbolAddress((void**)&p_Z, g_Z);
    cudaGetSymbolAddress((void**)&p_pacc, g_pacc);
    cudaGetSymbolAddress((void**)&p_pden, g_pden);
    cudaGetSymbolAddress((void**)&p_rv, g_rowvals);
    cudaGetSymbolAddress((void**)&p_cv, g_colvals);
    cudaGetSymbolAddress((void**)&p_bits, g_adjbits);

    // dynamic smem: 2*(Ws 32*136 + hs 32*(DC+8)) words + cvs(1KB) + dpar(1KB)
    const int smem256 = (2 * 32 * 136 + 2 * 32 * 136) * 4 + 2048;  // 71680
    const int smem64  = (2 * 32 * 136 + 2 * 32 * 72) * 4 + 2048;   // 55296
    cudaFuncSetAttribute((const void*)attn6_kernel<DH1, 128, 2, 4, 2>,
                         cudaFuncAttributeMaxDynamicSharedMemorySize, smem256);
    cudaFuncSetAttribute((const void*)attn6_kernel<DH2, 64, 1, 8, 1>,
                         cudaFuncAttributeMaxDynamicSharedMemorySize, smem64);

    // adjacency bitmask
    pack_adj_kernel<<<NN * NN / 256, 256>>>(adj, p_bits);

    // ---- layer 0: h0 = X@W0 ; hidden = attn(h0) ----
    gemm64_kernel<<<dim3(DH1 / 64, NN / 64), 256>>>(X, W0, p_h0, NN, DIN, DH1);
    vals_kernel<<<NN / 8, 256>>>(p_h0, a0, DH1, p_rv, p_cv);
    attn6_kernel<DH1, 128, 2, 4, 2><<<dim3(NN / 128, 2, 4), 256, smem256>>>(p_h0, p_rv, p_cv, p_bits, p_pacc, p_pden);
    combine_kernel<<<NN * DH1 / 4 / 256, 256>>>(p_pacc, p_pden, p_hidden, DH1, 4);

    // ---- layer 1 (mean) ----
    gemm64_kernel<<<dim3(DH2 / 64, NN / 64), 256>>>(p_hidden, W1, p_h1, NN, DH1, DH2);
    vals_kernel<<<NN / 8, 256>>>(p_h1, a1, DH2, p_rv, p_cv);
    attn6_kernel<DH2, 64, 1, 8, 1><<<dim3(NN / 128, 1, 8), 256, smem64>>>(p_h1, p_rv, p_cv, p_bits, p_pacc, p_pden);
    combine_kernel<<<NN * DH2 / 4 / 256, 256>>>(p_pacc, p_pden, p_mean, DH2, 8);

    // ---- layer 2 (logstd) ----
    gemm64_kernel<<<dim3(DH2 / 64, NN / 64), 256>>>(p_hidden, W2, p_h2, NN, DH1, DH2);
    vals_kernel<<<NN / 8, 256>>>(p_h2, a2, DH2, p_rv, p_cv);
    attn6_kernel<DH2, 64, 1, 8, 1><<<dim3(NN / 128, 1, 8), 256, smem64>>>(p_h2, p_rv, p_cv, p_bits, p_pacc, p_pden);
    combine_kernel<<<NN * DH2 / 4 / 256, 256>>>(p_pacc, p_pden, p_logstd, DH2, 8);

    // ---- Z and decoder ----
    z_kernel<<<NN * DH2 / 256, 256>>>(noise, p_logstd, p_mean, p_Z);
    zzt_kernel<<<dim3(NN / 64, NN / 64), 256>>>(p_Z, out);
}

// round 8
// speedup vs baseline: 1.2976x; 1.1678x over previous
#include <cuda_runtime.h>
#include <cuda_bf16.h>

#define NN 4096
#define DIN 512
#define DH1 256
#define DH2 64
#define ALPHA 0.2f

__device__ __forceinline__ unsigned f2tf(float f) {
    unsigned u; asm("cvt.rna.tf32.f32 %0, %1;" : "=r"(u) : "f"(f)); return u;
}
__device__ __forceinline__ void mma_tf32(float* c, const unsigned* a, unsigned b0, unsigned b1) {
    asm volatile("mma.sync.aligned.m16n8k8.row.col.f32.tf32.tf32.f32 "
                 "{%0,%1,%2,%3}, {%4,%5,%6,%7}, {%8,%9}, {%0,%1,%2,%3};"
                 : "+f"(c[0]), "+f"(c[1]), "+f"(c[2]), "+f"(c[3])
                 : "r"(a[0]), "r"(a[1]), "r"(a[2]), "r"(a[3]), "r"(b0), "r"(b1));
}

// MUFU-free sigmoid: exp2 via magic-round + poly, reciprocal via NR. fma/alu only.
__device__ __forceinline__ float fast_sigmoid(float x) {
    float u = -x * 1.44269504f;                 // 2^-u path: sigma = 1/(1+2^u)
    u = fminf(fmaxf(u, -60.f), 60.f);
    float s = u + 12582912.f;                   // round-to-nearest int in mantissa
    int n = __float_as_int(s) - 0x4B400000;
    float f = u - (s - 12582912.f);             // f in [-0.5, 0.5]
    float p = 0.00133336f;
    p = fmaf(p, f, 0.00961813f);
    p = fmaf(p, f, 0.05550411f);
    p = fmaf(p, f, 0.24022651f);
    p = fmaf(p, f, 0.69314718f);
    p = fmaf(p, f, 1.0f);                       // 2^f
    float e = __int_as_float(__float_as_int(p) + (n << 23));   // 2^u = e^{-x}
    float d = 1.f + e;
    float y = __int_as_float(0x7EF311C3 - __float_as_int(d));  // rcp seed
    y = y * fmaf(-d, y, 2.f);
    y = y * fmaf(-d, y, 2.f);
    return y;
}

// ---------------- device scratch (no allocations allowed) ----------------
__device__ float    g_h0[NN * DH1];
__device__ float    g_hidden[NN * DH1];
__device__ float    g_h1[NN * DH2];
__device__ float    g_h2[NN * DH2];
__device__ float    g_mean[NN * DH2];
__device__ float    g_logstd[NN * DH2];
__device__ float    g_Z[NN * DH2];
__device__ float4   g_rowvals[NN];
__device__ float4   g_colvals[NN];
__device__ unsigned g_adjbits[NN * (NN / 32)];
__device__ float    g_pacc[8 * NN * DH1];
__device__ float    g_pden[16 * NN];

// ---------------- pack adjacency into bitmask (2 MB, L2-resident) --------
__global__ void pack_adj_kernel(const int* __restrict__ adj, unsigned* __restrict__ bits) {
    int idx = blockIdx.x * 256 + threadIdx.x;
    unsigned b = __ballot_sync(0xffffffffu, adj[idx] > 0);
    if ((threadIdx.x & 31) == 0) bits[idx >> 5] = b;
}

// ---------------- tf32 mma GEMM: C[M,N] = A[M,K] @ B[K,N] ---------------
// Block: 128 rows x 64 cols, 256 threads. A tile [128][36], B tile [32][68].
template<int K>
__global__ __launch_bounds__(256) void gemmtf_kernel(
    const float* __restrict__ A, const float* __restrict__ B, float* __restrict__ C, int N)
{
    __shared__ __align__(16) unsigned As[128 * 36];
    __shared__ __align__(16) unsigned Bs[32 * 68];
    const int tid = threadIdx.x, wid = tid >> 5, lane = tid & 31;
    const int grp = lane >> 2, tid4 = lane & 3;
    const int warpRow = wid & 3, warpCol = wid >> 2;
    const int m0 = blockIdx.x * 128, n0 = blockIdx.y * 64;

    float acc[2][4][4] = {};
    for (int k0 = 0; k0 < K; k0 += 32) {
        __syncthreads();
#pragma unroll
        for (int it = 0; it < 4; ++it) {
            int q = tid + it * 256;
            int r = q >> 3, c4 = (q & 7) * 4;
            float4 v = *(const float4*)&A[(size_t)(m0 + r) * K + k0 + c4];
            uint4 t;
            t.x = f2tf(v.x); t.y = f2tf(v.y); t.z = f2tf(v.z); t.w = f2tf(v.w);
            *(uint4*)&As[r * 36 + c4] = t;
        }
#pragma unroll
        for (int it = 0; it < 2; ++it) {
            int q = tid + it * 256;
            int r = q >> 4, c4 = (q & 15) * 4;
            float4 v = *(const float4*)&B[(size_t)(k0 + r) * N + n0 + c4];
            uint4 t;
            t.x = f2tf(v.x); t.y = f2tf(v.y); t.z = f2tf(v.z); t.w = f2tf(v.w);
            *(uint4*)&Bs[r * 68 + c4] = t;
        }
        __syncthreads();
#pragma unroll
        for (int kk = 0; kk < 4; ++kk) {
            int kb = kk * 8;
            unsigned af[2][4];
#pragma unroll
            for (int m = 0; m < 2; ++m) {
                int rb = (warpRow * 2 + m) * 16;
                af[m][0] = As[(rb + grp) * 36 + kb + tid4];
                af[m][1] = As[(rb + grp + 8) * 36 + kb + tid4];
                af[m][2] = As[(rb + grp) * 36 + kb + tid4 + 4];
                af[m][3] = As[(rb + grp + 8) * 36 + kb + tid4 + 4];
            }
#pragma unroll
            for (int n = 0; n < 4; ++n) {
                int nn = warpCol * 32 + n * 8;
                unsigned b0 = Bs[(kb + tid4) * 68 + nn + grp];
                unsigned b1 = Bs[(kb + tid4 + 4) * 68 + nn + grp];
                mma_tf32(acc[0][n], af[0], b0, b1);
                mma_tf32(acc[1][n], af[1], b0, b1);
            }
        }
    }
#pragma unroll
    for (int m = 0; m < 2; ++m) {
        int r0 = m0 + (warpRow * 2 + m) * 16 + grp;
#pragma unroll
        for (int n = 0; n < 4; ++n) {
            int col = n0 + warpCol * 32 + n * 8 + 2 * tid4;
            *(float2*)&C[(size_t)r0 * N + col] = make_float2(acc[m][n][0], acc[m][n][1]);
            *(float2*)&C[(size_t)(r0 + 8) * N + col] = make_float2(acc[m][n][2], acc[m][n][3]);
        }
    }
}

// ---------------- per-row attention scalars ------------------------------
__global__ void vals_kernel(const float* __restrict__ h, const float* __restrict__ a,
                            int D, float4* __restrict__ rowvals, float4* __restrict__ colvals)
{
    int warp = (blockIdx.x * blockDim.x + threadIdx.x) >> 5;
    int lane = threadIdx.x & 31;
    if (warp >= NN) return;
    float s1 = 0.f, s2 = 0.f;
    for (int d = lane; d < D; d += 32) {
        float hv = h[(size_t)warp * D + d];
        s1 += hv * a[d];
        s2 += hv * a[D + d];
    }
#pragma unroll
    for (int o = 16; o; o >>= 1) {
        s1 += __shfl_xor_sync(0xffffffffu, s1, o);
        s2 += __shfl_xor_sync(0xffffffffu, s2, o);
    }
    if (lane == 0) {
        rowvals[warp] = make_float4(-s1, expf(s1), expf(ALPHA * s1), 0.f);
        colvals[warp] = make_float4(s2, expf(s2), expf(ALPHA * s2), 0.f);
    }
}

// ---------------- attention v6 (unchanged from R6) -----------------------
template<int D, int DC, int MT, int ROWG, int COLG>
__global__ __launch_bounds__(256, 2) void attn6_kernel(
    const float* __restrict__ h,
    const float4* __restrict__ rowvals,
    const float4* __restrict__ colvals,
    const unsigned* __restrict__ adjbits,
    float* __restrict__ pacc,
    float* __restrict__ pden)
{
    constexpr int BI = 128, BJ = 32, BIp = 136;
    constexpr int DCp = DC + 8;
    constexpr int NT = DC / COLG / 8;
    constexpr int WSF1 = BJ * BIp;
    constexpr int HSF1 = BJ * DCp;
    constexpr int LD_IT = BJ * DC / (4 * 256);

    extern __shared__ __align__(16) unsigned smem_u[];
    unsigned* Ws = smem_u;
    unsigned* hs = smem_u + 2 * WSF1;
    float4*   cvs = (float4*)(smem_u + 2 * WSF1 + 2 * HSF1);
    float*    dpar = (float*)(smem_u + 2 * WSF1 + 2 * HSF1 + 256);

    const int tid = threadIdx.x;
    const int wid = tid >> 5, lane = tid & 31;
    const int grp = lane >> 2, tid4 = lane & 3;
    const int warpRow = wid % ROWG, warpCol = wid / ROWG;
    const int rowbase = blockIdx.x * BI;
    const int colbase = blockIdx.y * DC;
    const int split = blockIdx.z;
    const int jcnt = NN / gridDim.z;
    const int jbeg = split * jcnt;
    const int T = jcnt / BJ;

    const int iA = tid & 127;
    const int jAb = (tid >> 7) * 16;
    const float4 rv = rowvals[rowbase + iA];
    float den = 0.f;

    float acc[MT][NT][4];
#pragma unroll
    for (int m = 0; m < MT; ++m)
#pragma unroll
        for (int n = 0; n < NT; ++n)
#pragma unroll
            for (int q = 0; q < 4; ++q) acc[m][n][q] = 0.f;

    auto ldg_tile = [&](int t, float4* v, float4& c4, unsigned& mw) {
        const int j0 = jbeg + t * BJ;
#pragma unroll
        for (int it = 0; it < LD_IT; ++it) {
            int q = tid + it * 256;
            int row = q / (DC / 4);
            int c = (q % (DC / 4)) * 4;
            v[it] = *(const float4*)&h[(size_t)(j0 + row) * D + colbase + c];
        }
        if (tid < 32) c4 = colvals[j0 + tid];
        mw = adjbits[(size_t)(rowbase + iA) * (NN / 32) + (j0 >> 5)];
    };
    auto sts_tile = [&](int buf, const float4* v, const float4& c4) {
        unsigned* hb = hs + buf * HSF1;
#pragma unroll
        for (int it = 0; it < LD_IT; ++it) {
            int q = tid + it * 256;
            int row = q / (DC / 4);
            int c = (q % (DC / 4)) * 4;
            uint4 t4;
            t4.x = f2tf(v[it].x); t4.y = f2tf(v[it].y);
            t4.z = f2tf(v[it].z); t4.w = f2tf(v[it].w);
            *(uint4*)&hb[row * DCp + c] = t4;
        }
        if (tid < 32) cvs[buf * 32 + tid] = c4;
    };
    auto phaseA = [&](int buf, unsigned mw) {
        unsigned* Wb = Ws + buf * WSF1;
        const float4* cv = cvs + buf * 32;
        const unsigned msk = mw >> jAb;
#pragma unroll
        for (int e = 0; e < 16; ++e) {
            int j = jAb + e;
            float4 c = cv[j];
            bool p = c.x > rv.x;
            float w = p ? (rv.y * c.y) : (rv.z * c.z);
            w = ((msk >> e) & 1u) ? w : 0.f;
            den += w;
            Wb[j * BIp + iA] = f2tf(w);
        }
    };
    auto phaseB = [&](int buf) {
        const unsigned* Wb = Ws + buf * WSF1;
        const unsigned* hb = hs + buf * HSF1;
#pragma unroll
        for (int k0 = 0; k0 < BJ; k0 += 8) {
            unsigned afr[MT][4];
#pragma unroll
            for (int m = 0; m < MT; ++m) {
                int rb = (warpRow * MT + m) * 16;
                afr[m][0] = Wb[(k0 + tid4) * BIp + rb + grp];
                afr[m][1] = Wb[(k0 + tid4) * BIp + rb + grp + 8];
                afr[m][2] = Wb[(k0 + tid4 + 4) * BIp + rb + grp];
                afr[m][3] = Wb[(k0 + tid4 + 4) * BIp + rb + grp + 8];
            }
#pragma unroll
            for (int n = 0; n < NT; ++n) {
                int n0 = warpCol * (NT * 8) + n * 8;
                unsigned b0 = hb[(k0 + tid4) * DCp + n0 + grp];
                unsigned b1 = hb[(k0 + tid4 + 4) * DCp + n0 + grp];
#pragma unroll
                for (int m = 0; m < MT; ++m)
                    mma_tf32(acc[m][n], afr[m], b0, b1);
            }
        }
    };

    {
        float4 v[LD_IT]; float4 c4 = make_float4(0, 0, 0, 0); unsigned mw;
        ldg_tile(0, v, c4, mw);
        sts_tile(0, v, c4);
        __syncthreads();
        phaseA(0, mw);
    }

    for (int t = 0; t < T; ++t) {
        const int cur = t & 1, nxt = cur ^ 1;
        __syncthreads();
        float4 v[LD_IT]; float4 c4 = make_float4(0, 0, 0, 0); unsigned mw = 0;
        const bool more = (t + 1 < T);
        if (more) ldg_tile(t + 1, v, c4, mw);
        phaseB(cur);
        if (more) sts_tile(nxt, v, c4);
        __syncthreads();
        if (more) phaseA(nxt, mw);
    }

#pragma unroll
    for (int m = 0; m < MT; ++m) {
        int r0 = rowbase + (warpRow * MT + m) * 16 + grp;
#pragma unroll
        for (int n = 0; n < NT; ++n) {
            int col = colbase + warpCol * (NT * 8) + n * 8 + 2 * tid4;
            float* p0 = pacc + ((size_t)split * NN + r0) * D + col;
            float* p1 = pacc + ((size_t)split * NN + r0 + 8) * D + col;
            *(float2*)p0 = make_float2(acc[m][n][0], acc[m][n][1]);
            *(float2*)p1 = make_float2(acc[m][n][2], acc[m][n][3]);
        }
    }
    dpar[tid] = den;
    __syncthreads();
    if (blockIdx.y == 0 && tid < BI)
        pden[split * NN + rowbase + tid] = dpar[tid] + dpar[tid + 128];
}

// ---------------- combine split partials + normalize ---------------------
__global__ void combine_kernel(const float* __restrict__ pacc, const float* __restrict__ pden,
                               float* __restrict__ out, int D, int nsplit)
{
    int idx = blockIdx.x * blockDim.x + threadIdx.x;
    int total = NN * D / 4;
    if (idx >= total) return;
    int row = idx / (D / 4);
    float4 s = make_float4(0.f, 0.f, 0.f, 0.f);
    float dd = 0.f;
    for (int sp = 0; sp < nsplit; ++sp) {
        float4 v = ((const float4*)pacc)[(size_t)sp * total + idx];
        s.x += v.x; s.y += v.y; s.z += v.z; s.w += v.w;
        dd += pden[sp * NN + row];
    }
    float inv = 1.f / dd;
    s.x *= inv; s.y *= inv; s.z *= inv; s.w *= inv;
    ((float4*)out)[idx] = s;
}

// ---------------- Z = noise * exp(logstd) + mean -------------------------
__global__ void z_kernel(const float* __restrict__ noise, const float* __restrict__ logstd,
                         const float* __restrict__ mean, float* __restrict__ Z)
{
    int idx = blockIdx.x * blockDim.x + threadIdx.x;
    if (idx >= NN * DH2) return;
    Z[idx] = noise[idx] * expf(logstd[idx]) + mean[idx];
}

// ---------------- A = sigmoid(Z @ Z^T): tf32 mma + MUFU-free sigmoid -----
__global__ __launch_bounds__(256, 2) void zzt2_kernel(const float* __restrict__ Z,
                                                      float* __restrict__ out)
{
    const int bi = blockIdx.y, bj = blockIdx.x;
    if (bj < bi) return;
    extern __shared__ __align__(16) unsigned zs[];
    unsigned* Zi = zs;                 // [128][68] tf32, [row][k]
    unsigned* Zj = zs + 128 * 68;      // [128][68]
    const int tid = threadIdx.x, wid = tid >> 5, lane = tid & 31;
    const int grp = lane >> 2, tid4 = lane & 3;
    const int warpRow = wid & 3, warpCol = wid >> 2;
    const int i0 = bi * 128, j0 = bj * 128;

    // load both tiles (Z is [NN][64] fp32): 2 tiles x 2048 float4
#pragma unroll
    for (int it = 0; it < 16; ++it) {
        int q = tid + it * 256;
        int tile = q >> 11;            // 0: Zi, 1: Zj
        int qq = q & 2047;
        int r = qq >> 4, c4 = (qq & 15) * 4;
        int gr = (tile ? j0 : i0) + r;
        float4 v = *(const float4*)&Z[(size_t)gr * DH2 + c4];
        uint4 t;
        t.x = f2tf(v.x); t.y = f2tf(v.y); t.z = f2tf(v.z); t.w = f2tf(v.w);
        *(uint4*)&((tile ? Zj : Zi)[r * 68 + c4]) = t;
    }
    __syncthreads();

    float acc[2][8][4] = {};
#pragma unroll
    for (int kk = 0; kk < 8; ++kk) {
        int kb = kk * 8;
        unsigned af[2][4];
#pragma unroll
        for (int m = 0; m < 2; ++m) {
            int rb = (warpRow * 2 + m) * 16;
            af[m][0] = Zi[(rb + grp) * 68 + kb + tid4];
            af[m][1] = Zi[(rb + grp + 8) * 68 + kb + tid4];
            af[m][2] = Zi[(rb + grp) * 68 + kb + tid4 + 4];
            af[m][3] = Zi[(rb + grp + 8) * 68 + kb + tid4 + 4];
        }
#pragma unroll
        for (int n = 0; n < 8; ++n) {
            int nn = warpCol * 64 + n * 8;
            unsigned b0 = Zj[(nn + grp) * 68 + kb + tid4];
            unsigned b1 = Zj[(nn + grp) * 68 + kb + tid4 + 4];
#pragma unroll
            for (int m = 0; m < 2; ++m)
                mma_tf32(acc[m][n], af[m], b0, b1);
        }
    }

    const bool mirror = (bj > bi);
#pragma unroll
    for (int m = 0; m < 2; ++m) {
        int r0 = i0 + (warpRow * 2 + m) * 16 + grp;
#pragma unroll
        for (int n = 0; n < 8; ++n) {
            int col = j0 + warpCol * 64 + n * 8 + 2 * tid4;
            float v0 = fast_sigmoid(acc[m][n][0]);
            float v1 = fast_sigmoid(acc[m][n][1]);
            float v2 = fast_sigmoid(acc[m][n][2]);
            float v3 = fast_sigmoid(acc[m][n][3]);
            *(float2*)&out[(size_t)r0 * NN + col] = make_float2(v0, v1);
            *(float2*)&out[(size_t)(r0 + 8) * NN + col] = make_float2(v2, v3);
            if (mirror) {
                out[(size_t)col * NN + r0] = v0;
                out[(size_t)(col + 1) * NN + r0] = v1;
                out[(size_t)col * NN + r0 + 8] = v2;
                out[(size_t)(col + 1) * NN + r0 + 8] = v3;
            }
        }
    }
}

// ---------------- host orchestration -------------------------------------
extern "C" void kernel_launch(void* const* d_in, const int* in_sizes, int n_in,
                              void* d_out, int out_size)
{
    const float* X     = (const float*)d_in[0];
    const int*   adj   = (const int*)  d_in[1];
    const float* noise = (const float*)d_in[2];
    const float* W0    = (const float*)d_in[3];
    const float* a0    = (const float*)d_in[4];
    const float* W1    = (const float*)d_in[5];
    const float* a1    = (const float*)d_in[6];
    const float* W2    = (const float*)d_in[7];
    const float* a2    = (const float*)d_in[8];
    float* out = (float*)d_out;

    float *p_h0, *p_hidden, *p_h1, *p_h2, *p_mean, *p_logstd, *p_Z, *p_pacc, *p_pden;
    float4 *p_rv, *p_cv;
    unsigned* p_bits;
    cudaGetSymbolAddress((void**)&p_h0, g_h0);
    cudaGetSymbolAddress((void**)&p_hidden, g_hidden);
    cudaGetSymbolAddress((void**)&p_h1, g_h1);
    cudaGetSymbolAddress((void**)&p_h2, g_h2);
    cudaGetSymbolAddress((void**)&p_mean, g_mean);
    cudaGetSymbolAddress((void**)&p_logstd, g_logstd);
    cudaGetSymbolAddress((void**)&p_Z, g_Z);
    cudaGetSymbolAddress((void**)&p_pacc, g_pacc);
    cudaGetSymbolAddress((void**)&p_pden, g_pden);
    cudaGetSymbolAddress((void**)&p_rv, g_rowvals);
    cudaGetSymbolAddress((void**)&p_cv, g_colvals);
    cudaGetSymbolAddress((void**)&p_bits, g_adjbits);

    const int smem256 = (2 * 32 * 136 + 2 * 32 * 136) * 4 + 2048;  // 71680
    const int smem64  = (2 * 32 * 136 + 2 * 32 * 72) * 4 + 2048;   // 55296
    const int smemZZ  = 2 * 128 * 68 * 4;                          // 69632
    cudaFuncSetAttribute((const void*)attn6_kernel<DH1, 128, 2, 4, 2>,
                         cudaFuncAttributeMaxDynamicSharedMemorySize, smem256);
    cudaFuncSetAttribute((const void*)attn6_kernel<DH2, 64, 1, 8, 1>,
                         cudaFuncAttributeMaxDynamicSharedMemorySize, smem64);
    cudaFuncSetAttribute((const void*)zzt2_kernel,
                         cudaFuncAttributeMaxDynamicSharedMemorySize, smemZZ);

    // adjacency bitmask
    pack_adj_kernel<<<NN * NN / 256, 256>>>(adj, p_bits);

    // ---- layer 0: h0 = X@W0 ; hidden = attn(h0) ----
    gemmtf_kernel<DIN><<<dim3(NN / 128, DH1 / 64), 256>>>(X, W0, p_h0, DH1);
    vals_kernel<<<NN / 8, 256>>>(p_h0, a0, DH1, p_rv, p_cv);
    attn6_kernel<DH1, 128, 2, 4, 2><<<dim3(NN / 128, 2, 4), 256, smem256>>>(p_h0, p_rv, p_cv, p_bits, p_pacc, p_pden);
    combine_kernel<<<NN * DH1 / 4 / 256, 256>>>(p_pacc, p_pden, p_hidden, DH1, 4);

    // ---- layer 1 (mean) ----
    gemmtf_kernel<DH1><<<dim3(NN / 128, 1), 256>>>(p_hidden, W1, p_h1, DH2);
    vals_kernel<<<NN / 8, 256>>>(p_h1, a1, DH2, p_rv, p_cv);
    attn6_kernel<DH2, 64, 1, 8, 1><<<dim3(NN / 128, 1, 8), 256, smem64>>>(p_h1, p_rv, p_cv, p_bits, p_pacc, p_pden);
    combine_kernel<<<NN * DH2 / 4 / 256, 256>>>(p_pacc, p_pden, p_mean, DH2, 8);

    // ---- layer 2 (logstd) ----
    gemmtf_kernel<DH1><<<dim3(NN / 128, 1), 256>>>(p_hidden, W2, p_h2, DH2);
    vals_kernel<<<NN / 8, 256>>>(p_h2, a2, DH2, p_rv, p_cv);
    attn6_kernel<DH2, 64, 1, 8, 1><<<dim3(NN / 128, 1, 8), 256, smem64>>>(p_h2, p_rv, p_cv, p_bits, p_pacc, p_pden);
    combine_kernel<<<NN * DH2 / 4 / 256, 256>>>(p_pacc, p_pden, p_logstd, DH2, 8);

    // ---- Z and decoder ----
    z_kernel<<<NN * DH2 / 256, 256>>>(noise, p_logstd, p_mean, p_Z);
    zzt2_kernel<<<dim3(NN / 128, NN / 128), 256, smemZZ>>>(p_Z, out);
}

// round 10
// speedup vs baseline: 1.3266x; 1.0224x over previous
#include <cuda_runtime.h>
#include <cuda_bf16.h>

#define NN 4096
#define DIN 512
#define DH1 256
#define DH2 64
#define ALPHA 0.2f

__device__ __forceinline__ unsigned f2tf(float f) {
    unsigned u; asm("cvt.rna.tf32.f32 %0, %1;" : "=r"(u) : "f"(f)); return u;
}
__device__ __forceinline__ void mma_tf32(float* c, const unsigned* a, unsigned b0, unsigned b1) {
    asm volatile("mma.sync.aligned.m16n8k8.row.col.f32.tf32.tf32.f32 "
                 "{%0,%1,%2,%3}, {%4,%5,%6,%7}, {%8,%9}, {%0,%1,%2,%3};"
                 : "+f"(c[0]), "+f"(c[1]), "+f"(c[2]), "+f"(c[3])
                 : "r"(a[0]), "r"(a[1]), "r"(a[2]), "r"(a[3]), "r"(b0), "r"(b1));
}
__device__ __forceinline__ void cp_async16(void* dst_smem, const void* src) {
    unsigned d = (unsigned)__cvta_generic_to_shared(dst_smem);
    asm volatile("cp.async.cg.shared.global [%0], [%1], 16;" :: "r"(d), "l"(src));
}
#define CP_COMMIT() asm volatile("cp.async.commit_group;")
#define CP_WAIT0()  asm volatile("cp.async.wait_group 0;")

// MUFU-free sigmoid: exp2 via magic-round + poly, reciprocal via NR. fma/alu only.
__device__ __forceinline__ float fast_sigmoid(float x) {
    float u = -x * 1.44269504f;
    u = fminf(fmaxf(u, -60.f), 60.f);
    float s = u + 12582912.f;
    int n = __float_as_int(s) - 0x4B400000;
    float f = u - (s - 12582912.f);
    float p = 0.00133336f;
    p = fmaf(p, f, 0.00961813f);
    p = fmaf(p, f, 0.05550411f);
    p = fmaf(p, f, 0.24022651f);
    p = fmaf(p, f, 0.69314718f);
    p = fmaf(p, f, 1.0f);
    float e = __int_as_float(__float_as_int(p) + (n << 23));
    float d = 1.f + e;
    float y = __int_as_float(0x7EF311C3 - __float_as_int(d));
    y = y * fmaf(-d, y, 2.f);
    y = y * fmaf(-d, y, 2.f);
    return y;
}

// ---------------- device scratch (no allocations allowed) ----------------
__device__ float    g_h0[NN * DH1];
__device__ unsigned g_h0t[NN * DH1];
__device__ float    g_hidden[NN * DH1];
__device__ float    g_h1[NN * DH2];
__device__ unsigned g_h1t[NN * DH2];
__device__ float    g_h2[NN * DH2];
__device__ unsigned g_h2t[NN * DH2];
__device__ float    g_mean[NN * DH2];
__device__ float    g_logstd[NN * DH2];
__device__ float    g_Z[NN * DH2];
__device__ float4   g_rowvals[NN];
__device__ float4   g_colvals[NN];
__device__ unsigned g_adjbits[NN * (NN / 32)];
__device__ float    g_pacc[8 * NN * DH1];
__device__ float    g_pden[16 * NN];

// ---------------- pack adjacency into bitmask ----------------------------
__global__ void pack_adj_kernel(const int* __restrict__ adj, unsigned* __restrict__ bits) {
    int idx = blockIdx.x * 256 + threadIdx.x;
    unsigned b = __ballot_sync(0xffffffffu, adj[idx] > 0);
    if ((threadIdx.x & 31) == 0) bits[idx >> 5] = b;
}

// ---------------- tf32 mma GEMM with dual (fp32 + tf32) output -----------
template<int K>
__global__ __launch_bounds__(256) void gemmtf_kernel(
    const float* __restrict__ A, const float* __restrict__ B,
    float* __restrict__ C, unsigned* __restrict__ Ct, int N)
{
    __shared__ __align__(16) unsigned As[128 * 36];
    __shared__ __align__(16) unsigned Bs[32 * 68];
    const int tid = threadIdx.x, wid = tid >> 5, lane = tid & 31;
    const int grp = lane >> 2, tid4 = lane & 3;
    const int warpRow = wid & 3, warpCol = wid >> 2;
    const int m0 = blockIdx.x * 128, n0 = blockIdx.y * 64;

    float acc[2][4][4] = {};
    for (int k0 = 0; k0 < K; k0 += 32) {
        __syncthreads();
#pragma unroll
        for (int it = 0; it < 4; ++it) {
            int q = tid + it * 256;
            int r = q >> 3, c4 = (q & 7) * 4;
            float4 v = *(const float4*)&A[(size_t)(m0 + r) * K + k0 + c4];
            uint4 t;
            t.x = f2tf(v.x); t.y = f2tf(v.y); t.z = f2tf(v.z); t.w = f2tf(v.w);
            *(uint4*)&As[r * 36 + c4] = t;
        }
#pragma unroll
        for (int it = 0; it < 2; ++it) {
            int q = tid + it * 256;
            int r = q >> 4, c4 = (q & 15) * 4;
            float4 v = *(const float4*)&B[(size_t)(k0 + r) * N + n0 + c4];
            uint4 t;
            t.x = f2tf(v.x); t.y = f2tf(v.y); t.z = f2tf(v.z); t.w = f2tf(v.w);
            *(uint4*)&Bs[r * 68 + c4] = t;
        }
        __syncthreads();
#pragma unroll
        for (int kk = 0; kk < 4; ++kk) {
            int kb = kk * 8;
            unsigned af[2][4];
#pragma unroll
            for (int m = 0; m < 2; ++m) {
                int rb = (warpRow * 2 + m) * 16;
                af[m][0] = As[(rb + grp) * 36 + kb + tid4];
                af[m][1] = As[(rb + grp + 8) * 36 + kb + tid4];
                af[m][2] = As[(rb + grp) * 36 + kb + tid4 + 4];
                af[m][3] = As[(rb + grp + 8) * 36 + kb + tid4 + 4];
            }
#pragma unroll
            for (int n = 0; n < 4; ++n) {
                int nn = warpCol * 32 + n * 8;
                unsigned b0 = Bs[(kb + tid4) * 68 + nn + grp];
                unsigned b1 = Bs[(kb + tid4 + 4) * 68 + nn + grp];
                mma_tf32(acc[0][n], af[0], b0, b1);
                mma_tf32(acc[1][n], af[1], b0, b1);
            }
        }
    }
#pragma unroll
    for (int m = 0; m < 2; ++m) {
        int r0 = m0 + (warpRow * 2 + m) * 16 + grp;
#pragma unroll
        for (int n = 0; n < 4; ++n) {
            int col = n0 + warpCol * 32 + n * 8 + 2 * tid4;
            float a0 = acc[m][n][0], a1 = acc[m][n][1];
            float a2 = acc[m][n][2], a3 = acc[m][n][3];
            *(float2*)&C[(size_t)r0 * N + col] = make_float2(a0, a1);
            *(float2*)&C[(size_t)(r0 + 8) * N + col] = make_float2(a2, a3);
            *(uint2*)&Ct[(size_t)r0 * N + col] = make_uint2(f2tf(a0), f2tf(a1));
            *(uint2*)&Ct[(size_t)(r0 + 8) * N + col] = make_uint2(f2tf(a2), f2tf(a3));
        }
    }
}

// ---------------- per-row attention scalars ------------------------------
__global__ void vals_kernel(const float* __restrict__ h, const float* __restrict__ a,
                            int D, float4* __restrict__ rowvals, float4* __restrict__ colvals)
{
    int warp = (blockIdx.x * blockDim.x + threadIdx.x) >> 5;
    int lane = threadIdx.x & 31;
    if (warp >= NN) return;
    float s1 = 0.f, s2 = 0.f;
    for (int d = lane; d < D; d += 32) {
        float hv = h[(size_t)warp * D + d];
        s1 += hv * a[d];
        s2 += hv * a[D + d];
    }
#pragma unroll
    for (int o = 16; o; o >>= 1) {
        s1 += __shfl_xor_sync(0xffffffffu, s1, o);
        s2 += __shfl_xor_sync(0xffffffffu, s2, o);
    }
    if (lane == 0) {
        rowvals[warp] = make_float4(-s1, expf(s1), expf(ALPHA * s1), 0.f);
        colvals[warp] = make_float4(s2, expf(s2), expf(ALPHA * s2), 0.f);
    }
}

// ---------------- attention v9: cp.async 3-ring, 2 barriers per tile -----
// Ring invariant: cp(t+1) targets buf (t+1)%3 whose last reader phaseB(t-2)
// is fenced by the post-phaseB barrier of iter t-1. phaseA reads land after
// wait_group+barrier, so cross-thread cp.async data is visible.
template<int D, int DC, int MT, int ROWG, int COLG>
__global__ __launch_bounds__(256, 2) void attn9_kernel(
    const unsigned* __restrict__ ht,        // tf32 pre-converted h
    const float4* __restrict__ rowvals,
    const float4* __restrict__ colvals,
    const unsigned* __restrict__ adjbits,
    float* __restrict__ pacc,
    float* __restrict__ pden)
{
    constexpr int BI = 128, BJ = 32, BIp = 136;
    constexpr int DCp = DC + 8;
    constexpr int NT = DC / (COLG * 8);
    constexpr int WS1 = BJ * BIp;
    constexpr int HS1 = BJ * DCp;
    constexpr int CP_IT = BJ * DC / (4 * 256);

    extern __shared__ __align__(16) unsigned smem_u[];
    unsigned* Ws = smem_u;                                    // [3][WS1]
    unsigned* hs = smem_u + 3 * WS1;                          // [3][HS1]
    float4*   cvs = (float4*)(smem_u + 3 * WS1 + 3 * HS1);    // [3][32]
    float*    dpar = (float*)(smem_u + 3 * WS1 + 3 * HS1 + 384);

    const int tid = threadIdx.x;
    const int wid = tid >> 5, lane = tid & 31;
    const int grp = lane >> 2, tid4 = lane & 3;
    const int warpRow = wid % ROWG, warpCol = wid / ROWG;
    const int rowbase = blockIdx.x * BI;
    const int colbase = blockIdx.y * DC;
    const int split = blockIdx.z;
    const int jcnt = NN / gridDim.z;
    const int jbeg = split * jcnt;
    const int T = jcnt / BJ;

    const int iA = tid & 127;
    const int jAb = (tid >> 7) * 16;
    const float4 rv = rowvals[rowbase + iA];
    float den = 0.f;

    float acc[MT][NT][4];
#pragma unroll
    for (int m = 0; m < MT; ++m)
#pragma unroll
        for (int n = 0; n < NT; ++n)
#pragma unroll
            for (int q = 0; q < 4; ++q) acc[m][n][q] = 0.f;

    auto cp_tile = [&](int t, int buf) {
        const int j0 = jbeg + t * BJ;
        unsigned* hb = hs + buf * HS1;
#pragma unroll
        for (int it = 0; it < CP_IT; ++it) {
            int q = tid + it * 256;
            int row = q / (DC / 4);
            int c = (q % (DC / 4)) * 4;
            cp_async16(&hb[row * DCp + c], &ht[(size_t)(j0 + row) * D + colbase + c]);
        }
        if (tid < 32) cp_async16(&cvs[buf * 32 + tid], &colvals[j0 + tid]);
    };
    auto phaseA = [&](int buf, unsigned mw) {
        unsigned* Wb = Ws + buf * WS1;
        const float4* cv = cvs + buf * 32;
        const unsigned msk = mw >> jAb;
#pragma unroll
        for (int e = 0; e < 16; ++e) {
            int j = jAb + e;
            float4 c = cv[j];
            bool p = c.x > rv.x;
            float w = p ? (rv.y * c.y) : (rv.z * c.z);
            w = ((msk >> e) & 1u) ? w : 0.f;
            den += w;
            Wb[j * BIp + iA] = f2tf(w);
        }
    };
    auto phaseB = [&](int buf) {
        const unsigned* Wb = Ws + buf * WS1;
        const unsigned* hb = hs + buf * HS1;
#pragma unroll
        for (int k0 = 0; k0 < BJ; k0 += 8) {
            unsigned afr[MT][4];
#pragma unroll
            for (int m = 0; m < MT; ++m) {
                int rb = (warpRow * MT + m) * 16;
                afr[m][0] = Wb[(k0 + tid4) * BIp + rb + grp];
                afr[m][1] = Wb[(k0 + tid4) * BIp + rb + grp + 8];
                afr[m][2] = Wb[(k0 + tid4 + 4) * BIp + rb + grp];
                afr[m][3] = Wb[(k0 + tid4 + 4) * BIp + rb + grp + 8];
            }
#pragma unroll
            for (int n = 0; n < NT; ++n) {
                int n0 = warpCol * (NT * 8) + n * 8;
                unsigned b0 = hb[(k0 + tid4) * DCp + n0 + grp];
                unsigned b1 = hb[(k0 + tid4 + 4) * DCp + n0 + grp];
#pragma unroll
                for (int m = 0; m < MT; ++m)
                    mma_tf32(acc[m][n], afr[m], b0, b1);
            }
        }
    };

    // prologue: tile 0 copies landed + visible, then weights for tile 0
    {
        cp_tile(0, 0);
        CP_COMMIT();
        unsigned mw = adjbits[(size_t)(rowbase + iA) * (NN / 32) + (jbeg >> 5)];
        CP_WAIT0();
        __syncthreads();            // tile0 copies visible to all threads
        phaseA(0, mw);
    }

    for (int t = 0; t < T; ++t) {
        const int cur = t % 3;
        const bool more = (t + 1 < T);
        unsigned mw = 0;
        if (more) {
            cp_tile(t + 1, (t + 1) % 3);   // safe: buf (t+1)%3 last read at phaseB(t-2)
            CP_COMMIT();
            mw = adjbits[(size_t)(rowbase + iA) * (NN / 32) + ((jbeg + (t + 1) * BJ) >> 5)];
        }
        __syncthreads();            // Ws[cur] (phaseA(t)) visible; hs[cur] already visible
        phaseB(cur);
        if (more) {
            CP_WAIT0();             // own copies of tile t+1 done
            __syncthreads();        // ALL threads' tile t+1 copies visible; phaseB(t) fenced
            phaseA((t + 1) % 3, mw);
        }
    }

    // epilogue
#pragma unroll
    for (int m = 0; m < MT; ++m) {
        int r0 = rowbase + (warpRow * MT + m) * 16 + grp;
#pragma unroll
        for (int n = 0; n < NT; ++n) {
            int col = colbase + warpCol * (NT * 8) + n * 8 + 2 * tid4;
            float* p0 = pacc + ((size_t)split * NN + r0) * D + col;
            float* p1 = pacc + ((size_t)split * NN + r0 + 8) * D + col;
            *(float2*)p0 = make_float2(acc[m][n][0], acc[m][n][1]);
            *(float2*)p1 = make_float2(acc[m][n][2], acc[m][n][3]);
        }
    }
    dpar[tid] = den;
    __syncthreads();
    if (blockIdx.y == 0 && tid < BI)
        pden[split * NN + rowbase + tid] = dpar[tid] + dpar[tid + 128];
}

// ---------------- combine split partials + normalize ---------------------
__global__ void combine_kernel(const float* __restrict__ pacc, const float* __restrict__ pden,
                               float* __restrict__ out, int D, int nsplit)
{
    int idx = blockIdx.x * blockDim.x + threadIdx.x;
    int total = NN * D / 4;
    if (idx >= total) return;
    int row = idx / (D / 4);
    float4 s = make_float4(0.f, 0.f, 0.f, 0.f);
    float dd = 0.f;
    for (int sp = 0; sp < nsplit; ++sp) {
        float4 v = ((const float4*)pacc)[(size_t)sp * total + idx];
        s.x += v.x; s.y += v.y; s.z += v.z; s.w += v.w;
        dd += pden[sp * NN + row];
    }
    float inv = 1.f / dd;
    s.x *= inv; s.y *= inv; s.z *= inv; s.w *= inv;
    ((float4*)out)[idx] = s;
}

// ---------------- Z = noise * exp(logstd) + mean -------------------------
__global__ void z_kernel(const float* __restrict__ noise, const float* __restrict__ logstd,
                         const float* __restrict__ mean, float* __restrict__ Z)
{
    int idx = blockIdx.x * blockDim.x + threadIdx.x;
    if (idx >= NN * DH2) return;
    Z[idx] = noise[idx] * expf(logstd[idx]) + mean[idx];
}

// ---------------- A = sigmoid(Z @ Z^T): tf32 mma, coalesced mirror -------
__global__ __launch_bounds__(256, 2) void zzt2_kernel(const float* __restrict__ Z,
                                                      float* __restrict__ out)
{
    const int bi = blockIdx.y, bj = blockIdx.x;
    if (bj < bi) return;
    extern __shared__ __align__(16) unsigned zs[];
    unsigned* Zi = zs;                 // [128][68]
    unsigned* Zj = zs + 128 * 68;      // [128][68]
    const int tid = threadIdx.x, wid = tid >> 5, lane = tid & 31;
    const int grp = lane >> 2, tid4 = lane & 3;
    const int warpRow = wid & 3, warpCol = wid >> 2;
    const int i0 = bi * 128, j0 = bj * 128;

#pragma unroll
    for (int it = 0; it < 16; ++it) {
        int q = tid + it * 256;
        int tile = q >> 11;
        int qq = q & 2047;
        int r = qq >> 4, c4 = (qq & 15) * 4;
        int gr = (tile ? j0 : i0) + r;
        float4 v = *(const float4*)&Z[(size_t)gr * DH2 + c4];
        uint4 t;
        t.x = f2tf(v.x); t.y = f2tf(v.y); t.z = f2tf(v.z); t.w = f2tf(v.w);
        *(uint4*)&((tile ? Zj : Zi)[r * 68 + c4]) = t;
    }
    __syncthreads();

    float acc[2][8][4] = {};
#pragma unroll
    for (int kk = 0; kk < 8; ++kk) {
        int kb = kk * 8;
        unsigned af[2][4];
#pragma unroll
        for (int m = 0; m < 2; ++m) {
            int rb = (warpRow * 2 + m) * 16;
            af[m][0] = Zi[(rb + grp) * 68 + kb + tid4];
            af[m][1] = Zi[(rb + grp + 8) * 68 + kb + tid4];
            af[m][2] = Zi[(rb + grp) * 68 + kb + tid4 + 4];
            af[m][3] = Zi[(rb + grp + 8) * 68 + kb + tid4 + 4];
        }
#pragma unroll
        for (int n = 0; n < 8; ++n) {
            int nn = warpCol * 64 + n * 8;
            unsigned b0 = Zj[(nn + grp) * 68 + kb + tid4];
            unsigned b1 = Zj[(nn + grp) * 68 + kb + tid4 + 4];
#pragma unroll
            for (int m = 0; m < 2; ++m)
                mma_tf32(acc[m][n], af[m], b0, b1);
        }
    }

    // sigmoid in place; write own tile coalesced
#pragma unroll
    for (int m = 0; m < 2; ++m) {
        int r0 = i0 + (warpRow * 2 + m) * 16 + grp;
#pragma unroll
        for (int n = 0; n < 8; ++n) {
            int col = j0 + warpCol * 64 + n * 8 + 2 * tid4;
#pragma unroll
            for (int q = 0; q < 4; ++q) acc[m][n][q] = fast_sigmoid(acc[m][n][q]);
            *(float2*)&out[(size_t)r0 * NN + col] = make_float2(acc[m][n][0], acc[m][n][1]);
            *(float2*)&out[(size_t)(r0 + 8) * NN + col] = make_float2(acc[m][n][2], acc[m][n][3]);
        }
    }

    if (bj > bi) {
        // stage transposed tile in smem (reuse Zi/Zj: 128x132 floats fits), write coalesced
        __syncthreads();                 // done reading Zi/Zj
        float* sT = (float*)zs;          // [128 cols][132]
#pragma unroll
        for (int m = 0; m < 2; ++m) {
            int lr0 = (warpRow * 2 + m) * 16 + grp;
#pragma unroll
            for (int n = 0; n < 8; ++n) {
                int lc = warpCol * 64 + n * 8 + 2 * tid4;
                sT[(size_t)lc * 132 + lr0] = acc[m][n][0];
                sT[(size_t)(lc + 1) * 132 + lr0] = acc[m][n][1];
                sT[(size_t)lc * 132 + lr0 + 8] = acc[m][n][2];
                sT[(size_t)(lc + 1) * 132 + lr0 + 8] = acc[m][n][3];
            }
        }
        __syncthreads();
#pragma unroll
        for (int it = 0; it < 16; ++it) {
            int q = tid + it * 256;
            int rr = q >> 5, cc = (q & 31) * 4;
            float4 v = *(float4*)&sT[(size_t)rr * 132 + cc];
            *(float4*)&out[(size_t)(j0 + rr) * NN + i0 + cc] = v;
        }
    }
}

// ---------------- host orchestration -------------------------------------
extern "C" void kernel_launch(void* const* d_in, const int* in_sizes, int n_in,
                              void* d_out, int out_size)
{
    const float* X     = (const float*)d_in[0];
    const int*   adj   = (const int*)  d_in[1];
    const float* noise = (const float*)d_in[2];
    const float* W0    = (const float*)d_in[3];
    const float* a0    = (const float*)d_in[4];
    const float* W1    = (const float*)d_in[5];
    const float* a1    = (const float*)d_in[6];
    const float* W2    = (const float*)d_in[7];
    const float* a2    = (const float*)d_in[8];
    float* out = (float*)d_out;

    float *p_h0, *p_hidden, *p_h1, *p_h2, *p_mean, *p_logstd, *p_Z, *p_pacc, *p_pden;
    unsigned *p_h0t, *p_h1t, *p_h2t;
    float4 *p_rv, *p_cv;
    unsigned* p_bits;
    cudaGetSymbolAddress((void**)&p_h0, g_h0);
    cudaGetSymbolAddress((void**)&p_h0t, g_h0t);
    cudaGetSymbolAddress((void**)&p_hidden, g_hidden);
    cudaGetSymbolAddress((void**)&p_h1, g_h1);
    cudaGetSymbolAddress((void**)&p_h1t, g_h1t);
    cudaGetSymbolAddress((void**)&p_h2, g_h2);
    cudaGetSymbolAddress((void**)&p_h2t, g_h2t);
    cudaGetSymbolAddress((void**)&p_mean, g_mean);
    cudaGetSymbolAddress((void**)&p_logstd, g_logstd);
    cudaGetSymbolAddress((void**)&p_Z, g_Z);
    cudaGetSymbolAddress((void**)&p_pacc, g_pacc);
    cudaGetSymbolAddress((void**)&p_pden, g_pden);
    cudaGetSymbolAddress((void**)&p_rv, g_rowvals);
    cudaGetSymbolAddress((void**)&p_cv, g_colvals);
    cudaGetSymbolAddress((void**)&p_bits, g_adjbits);

    // smem: 3*(Ws 32*136) + 3*(hs 32*(DC+8)) words + cvs(3*32*16B) + dpar(1KB)
    const int smem256 = (3 * 32 * 136 + 3 * 32 * 136 + 384 + 256) * 4;  // 107008
    const int smem64  = (3 * 32 * 136 + 3 * 32 * 72 + 384 + 256) * 4;   // 82432
    const int smemZZ  = 2 * 128 * 68 * 4;                               // 69632
    cudaFuncSetAttribute((const void*)attn9_kernel<DH1, 128, 2, 4, 2>,
                         cudaFuncAttributeMaxDynamicSharedMemorySize, smem256);
    cudaFuncSetAttribute((const void*)attn9_kernel<DH2, 64, 1, 8, 1>,
                         cudaFuncAttributeMaxDynamicSharedMemorySize, smem64);
    cudaFuncSetAttribute((const void*)zzt2_kernel,
                         cudaFuncAttributeMaxDynamicSharedMemorySize, smemZZ);

    pack_adj_kernel<<<NN * NN / 256, 256>>>(adj, p_bits);

    // ---- layer 0 ----
    gemmtf_kernel<DIN><<<dim3(NN / 128, DH1 / 64), 256>>>(X, W0, p_h0, p_h0t, DH1);
    vals_kernel<<<NN / 8, 256>>>(p_h0, a0, DH1, p_rv, p_cv);
    attn9_kernel<DH1, 128, 2, 4, 2><<<dim3(NN / 128, 2, 4), 256, smem256>>>(p_h0t, p_rv, p_cv, p_bits, p_pacc, p_pden);
    combine_kernel<<<NN * DH1 / 4 / 256, 256>>>(p_pacc, p_pden, p_hidden, DH1, 4);

    // ---- layer 1 (mean) ----
    gemmtf_kernel<DH1><<<dim3(NN / 128, 1), 256>>>(p_hidden, W1, p_h1, p_h1t, DH2);
    vals_kernel<<<NN / 8, 256>>>(p_h1, a1, DH2, p_rv, p_cv);
    attn9_kernel<DH2, 64, 1, 8, 1><<<dim3(NN / 128, 1, 8), 256, smem64>>>(p_h1t, p_rv, p_cv, p_bits, p_pacc, p_pden);
    combine_kernel<<<NN * DH2 / 4 / 256, 256>>>(p_pacc, p_pden, p_mean, DH2, 8);

    // ---- layer 2 (logstd) ----
    gemmtf_kernel<DH1><<<dim3(NN / 128, 1), 256>>>(p_hidden, W2, p_h2, p_h2t, DH2);
    vals_kernel<<<NN / 8, 256>>>(p_h2, a2, DH2, p_rv, p_cv);
    attn9_kernel<DH2, 64, 1, 8, 1><<<dim3(NN / 128, 1, 8), 256, smem64>>>(p_h2t, p_rv, p_cv, p_bits, p_pacc, p_pden);
    combine_kernel<<<NN * DH2 / 4 / 256, 256>>>(p_pacc, p_pden, p_logstd, DH2, 8);

    // ---- Z and decoder ----
    z_kernel<<<NN * DH2 / 256, 256>>>(noise, p_logstd, p_mean, p_Z);
    zzt2_kernel<<<dim3(NN / 128, NN / 128), 256, smemZZ>>>(p_Z, out);
}

// round 11
// speedup vs baseline: 1.3282x; 1.0012x over previous
#include <cuda_runtime.h>
#include <cuda_bf16.h>

#define NN 4096
#define DIN 512
#define DH1 256
#define DH2 64
#define ALPHA 0.2f

__device__ __forceinline__ unsigned f2tf(float f) {
    unsigned u; asm("cvt.rna.tf32.f32 %0, %1;" : "=r"(u) : "f"(f)); return u;
}
__device__ __forceinline__ void mma_tf32(float* c, const unsigned* a, unsigned b0, unsigned b1) {
    asm volatile("mma.sync.aligned.m16n8k8.row.col.f32.tf32.tf32.f32 "
                 "{%0,%1,%2,%3}, {%4,%5,%6,%7}, {%8,%9}, {%0,%1,%2,%3};"
                 : "+f"(c[0]), "+f"(c[1]), "+f"(c[2]), "+f"(c[3])
                 : "r"(a[0]), "r"(a[1]), "r"(a[2]), "r"(a[3]), "r"(b0), "r"(b1));
}
__device__ __forceinline__ void cp_async16(void* dst_smem, const void* src) {
    unsigned d = (unsigned)__cvta_generic_to_shared(dst_smem);
    asm volatile("cp.async.cg.shared.global [%0], [%1], 16;" :: "r"(d), "l"(src));
}
#define CP_COMMIT() asm volatile("cp.async.commit_group;")
#define CP_WAIT0()  asm volatile("cp.async.wait_group 0;")

// fma/alu-only exp2-based exp and sigmoid
__device__ __forceinline__ float fast_exp(float x) {
    float u = x * 1.44269504f;
    u = fminf(fmaxf(u, -60.f), 60.f);
    float s = u + 12582912.f;
    int n = __float_as_int(s) - 0x4B400000;
    float f = u - (s - 12582912.f);
    float p = 0.00133336f;
    p = fmaf(p, f, 0.00961813f);
    p = fmaf(p, f, 0.05550411f);
    p = fmaf(p, f, 0.24022651f);
    p = fmaf(p, f, 0.69314718f);
    p = fmaf(p, f, 1.0f);
    return __int_as_float(__float_as_int(p) + (n << 23));
}
__device__ __forceinline__ float fast_sigmoid(float x) {
    float e = fast_exp(-x);
    float d = 1.f + e;
    float y = __int_as_float(0x7EF311C3 - __float_as_int(d));
    y = y * fmaf(-d, y, 2.f);
    y = y * fmaf(-d, y, 2.f);
    return y;
}

// ---------------- device scratch (no allocations allowed) ----------------
__device__ float    g_h0[NN * DH1];
__device__ unsigned g_h0t[NN * DH1];
__device__ float    g_hidden[NN * DH1];
__device__ float    g_h1[NN * DH2];
__device__ unsigned g_h1t[NN * DH2];
__device__ float    g_h2[NN * DH2];
__device__ unsigned g_h2t[NN * DH2];
__device__ float    g_Z[NN * DH2];
__device__ float4   g_rowvals[NN];
__device__ float4   g_colvals[NN];
__device__ float4   g_rowvals2[NN];
__device__ float4   g_colvals2[NN];
__device__ unsigned g_adjbits[NN * (NN / 32)];
__device__ float    g_pacc[8 * NN * DH1];    // layer0: 8 splits x N x 256 (exact)
__device__ float    g_pden[16 * NN];

// ---------------- pack adjacency into bitmask ----------------------------
__global__ void pack_adj_kernel(const int* __restrict__ adj, unsigned* __restrict__ bits) {
    int idx = blockIdx.x * 256 + threadIdx.x;
    unsigned b = __ballot_sync(0xffffffffu, adj[idx] > 0);
    if ((threadIdx.x & 31) == 0) bits[idx >> 5] = b;
}

// ---------------- tf32 mma GEMM with dual (fp32 + tf32) output -----------
template<int K>
__global__ __launch_bounds__(256) void gemmtf_kernel(
    const float* __restrict__ A, const float* __restrict__ B,
    float* __restrict__ C, unsigned* __restrict__ Ct, int N)
{
    __shared__ __align__(16) unsigned As[128 * 36];
    __shared__ __align__(16) unsigned Bs[32 * 68];
    const int tid = threadIdx.x, wid = tid >> 5, lane = tid & 31;
    const int grp = lane >> 2, tid4 = lane & 3;
    const int warpRow = wid & 3, warpCol = wid >> 2;
    const int m0 = blockIdx.x * 128, n0 = blockIdx.y * 64;

    float acc[2][4][4] = {};
    for (int k0 = 0; k0 < K; k0 += 32) {
        __syncthreads();
#pragma unroll
        for (int it = 0; it < 4; ++it) {
            int q = tid + it * 256;
            int r = q >> 3, c4 = (q & 7) * 4;
            float4 v = *(const float4*)&A[(size_t)(m0 + r) * K + k0 + c4];
            uint4 t;
            t.x = f2tf(v.x); t.y = f2tf(v.y); t.z = f2tf(v.z); t.w = f2tf(v.w);
            *(uint4*)&As[r * 36 + c4] = t;
        }
#pragma unroll
        for (int it = 0; it < 2; ++it) {
            int q = tid + it * 256;
            int r = q >> 4, c4 = (q & 15) * 4;
            float4 v = *(const float4*)&B[(size_t)(k0 + r) * N + n0 + c4];
            uint4 t;
            t.x = f2tf(v.x); t.y = f2tf(v.y); t.z = f2tf(v.z); t.w = f2tf(v.w);
            *(uint4*)&Bs[r * 68 + c4] = t;
        }
        __syncthreads();
#pragma unroll
        for (int kk = 0; kk < 4; ++kk) {
            int kb = kk * 8;
            unsigned af[2][4];
#pragma unroll
            for (int m = 0; m < 2; ++m) {
                int rb = (warpRow * 2 + m) * 16;
                af[m][0] = As[(rb + grp) * 36 + kb + tid4];
                af[m][1] = As[(rb + grp + 8) * 36 + kb + tid4];
                af[m][2] = As[(rb + grp) * 36 + kb + tid4 + 4];
                af[m][3] = As[(rb + grp + 8) * 36 + kb + tid4 + 4];
            }
#pragma unroll
            for (int n = 0; n < 4; ++n) {
                int nn = warpCol * 32 + n * 8;
                unsigned b0 = Bs[(kb + tid4) * 68 + nn + grp];
                unsigned b1 = Bs[(kb + tid4 + 4) * 68 + nn + grp];
                mma_tf32(acc[0][n], af[0], b0, b1);
                mma_tf32(acc[1][n], af[1], b0, b1);
            }
        }
    }
#pragma unroll
    for (int m = 0; m < 2; ++m) {
        int r0 = m0 + (warpRow * 2 + m) * 16 + grp;
#pragma unroll
        for (int n = 0; n < 4; ++n) {
            int col = n0 + warpCol * 32 + n * 8 + 2 * tid4;
            float a0 = acc[m][n][0], a1 = acc[m][n][1];
            float a2 = acc[m][n][2], a3 = acc[m][n][3];
            *(float2*)&C[(size_t)r0 * N + col] = make_float2(a0, a1);
            *(float2*)&C[(size_t)(r0 + 8) * N + col] = make_float2(a2, a3);
            *(uint2*)&Ct[(size_t)r0 * N + col] = make_uint2(f2tf(a0), f2tf(a1));
            *(uint2*)&Ct[(size_t)(r0 + 8) * N + col] = make_uint2(f2tf(a2), f2tf(a3));
        }
    }
}

// ---------------- per-row attention scalars ------------------------------
__global__ void vals_kernel(const float* __restrict__ h, const float* __restrict__ a,
                            int D, float4* __restrict__ rowvals, float4* __restrict__ colvals)
{
    int warp = (blockIdx.x * blockDim.x + threadIdx.x) >> 5;
    int lane = threadIdx.x & 31;
    if (warp >= NN) return;
    float s1 = 0.f, s2 = 0.f;
    for (int d = lane; d < D; d += 32) {
        float hv = h[(size_t)warp * D + d];
        s1 += hv * a[d];
        s2 += hv * a[D + d];
    }
#pragma unroll
    for (int o = 16; o; o >>= 1) {
        s1 += __shfl_xor_sync(0xffffffffu, s1, o);
        s2 += __shfl_xor_sync(0xffffffffu, s2, o);
    }
    if (lane == 0) {
        rowvals[warp] = make_float4(-s1, expf(s1), expf(ALPHA * s1), 0.f);
        colvals[warp] = make_float4(s2, expf(s2), expf(ALPHA * s2), 0.f);
    }
}

// ---------------- attention v9: cp.async 3-ring, 2 barriers per tile -----
template<int D, int DC, int MT, int ROWG, int COLG>
__global__ __launch_bounds__(256, 2) void attn9_kernel(
    const unsigned* __restrict__ ht,
    const float4* __restrict__ rowvals,
    const float4* __restrict__ colvals,
    const unsigned* __restrict__ adjbits,
    float* __restrict__ pacc,
    float* __restrict__ pden)
{
    constexpr int BI = 128, BJ = 32, BIp = 136;
    constexpr int DCp = DC + 8;
    constexpr int NT = DC / (COLG * 8);
    constexpr int WS1 = BJ * BIp;
    constexpr int HS1 = BJ * DCp;
    constexpr int CP_IT = BJ * DC / (4 * 256);

    extern __shared__ __align__(16) unsigned smem_u[];
    unsigned* Ws = smem_u;
    unsigned* hs = smem_u + 3 * WS1;
    float4*   cvs = (float4*)(smem_u + 3 * WS1 + 3 * HS1);
    float*    dpar = (float*)(smem_u + 3 * WS1 + 3 * HS1 + 384);

    const int tid = threadIdx.x;
    const int wid = tid >> 5, lane = tid & 31;
    const int grp = lane >> 2, tid4 = lane & 3;
    const int warpRow = wid % ROWG, warpCol = wid / ROWG;
    const int rowbase = blockIdx.x * BI;
    const int colbase = blockIdx.y * DC;
    const int split = blockIdx.z;
    const int jcnt = NN / gridDim.z;
    const int jbeg = split * jcnt;
    const int T = jcnt / BJ;

    const int iA = tid & 127;
    const int jAb = (tid >> 7) * 16;
    const float4 rv = rowvals[rowbase + iA];
    float den = 0.f;

    float acc[MT][NT][4];
#pragma unroll
    for (int m = 0; m < MT; ++m)
#pragma unroll
        for (int n = 0; n < NT; ++n)
#pragma unroll
            for (int q = 0; q < 4; ++q) acc[m][n][q] = 0.f;

    auto cp_tile = [&](int t, int buf) {
        const int j0 = jbeg + t * BJ;
        unsigned* hb = hs + buf * HS1;
#pragma unroll
        for (int it = 0; it < CP_IT; ++it) {
            int q = tid + it * 256;
            int row = q / (DC / 4);
            int c = (q % (DC / 4)) * 4;
            cp_async16(&hb[row * DCp + c], &ht[(size_t)(j0 + row) * D + colbase + c]);
        }
        if (tid < 32) cp_async16(&cvs[buf * 32 + tid], &colvals[j0 + tid]);
    };
    auto phaseA = [&](int buf, unsigned mw) {
        unsigned* Wb = Ws + buf * WS1;
        const float4* cv = cvs + buf * 32;
        const unsigned msk = mw >> jAb;
#pragma unroll
        for (int e = 0; e < 16; ++e) {
            int j = jAb + e;
            float4 c = cv[j];
            bool p = c.x > rv.x;
            float w = p ? (rv.y * c.y) : (rv.z * c.z);
            w = ((msk >> e) & 1u) ? w : 0.f;
            den += w;
            Wb[j * BIp + iA] = f2tf(w);
        }
    };
    auto phaseB = [&](int buf) {
        const unsigned* Wb = Ws + buf * WS1;
        const unsigned* hb = hs + buf * HS1;
#pragma unroll
        for (int k0 = 0; k0 < BJ; k0 += 8) {
            unsigned afr[MT][4];
#pragma unroll
            for (int m = 0; m < MT; ++m) {
                int rb = (warpRow * MT + m) * 16;
                afr[m][0] = Wb[(k0 + tid4) * BIp + rb + grp];
                afr[m][1] = Wb[(k0 + tid4) * BIp + rb + grp + 8];
                afr[m][2] = Wb[(k0 + tid4 + 4) * BIp + rb + grp];
                afr[m][3] = Wb[(k0 + tid4 + 4) * BIp + rb + grp + 8];
            }
#pragma unroll
            for (int n = 0; n < NT; ++n) {
                int n0 = warpCol * (NT * 8) + n * 8;
                unsigned b0 = hb[(k0 + tid4) * DCp + n0 + grp];
                unsigned b1 = hb[(k0 + tid4 + 4) * DCp + n0 + grp];
#pragma unroll
                for (int m = 0; m < MT; ++m)
                    mma_tf32(acc[m][n], afr[m], b0, b1);
            }
        }
    };

    {
        cp_tile(0, 0);
        CP_COMMIT();
        unsigned mw = adjbits[(size_t)(rowbase + iA) * (NN / 32) + (jbeg >> 5)];
        CP_WAIT0();
        __syncthreads();
        phaseA(0, mw);
    }

    for (int t = 0; t < T; ++t) {
        const int cur = t % 3;
        const bool more = (t + 1 < T);
        unsigned mw = 0;
        if (more) {
            cp_tile(t + 1, (t + 1) % 3);
            CP_COMMIT();
            mw = adjbits[(size_t)(rowbase + iA) * (NN / 32) + ((jbeg + (t + 1) * BJ) >> 5)];
        }
        __syncthreads();
        phaseB(cur);
        if (more) {
            CP_WAIT0();
            __syncthreads();
            phaseA((t + 1) % 3, mw);
        }
    }

#pragma unroll
    for (int m = 0; m < MT; ++m) {
        int r0 = rowbase + (warpRow * MT + m) * 16 + grp;
#pragma unroll
        for (int n = 0; n < NT; ++n) {
            int col = colbase + warpCol * (NT * 8) + n * 8 + 2 * tid4;
            float* p0 = pacc + ((size_t)split * NN + r0) * D + col;
            float* p1 = pacc + ((size_t)split * NN + r0 + 8) * D + col;
            *(float2*)p0 = make_float2(acc[m][n][0], acc[m][n][1]);
            *(float2*)p1 = make_float2(acc[m][n][2], acc[m][n][3]);
        }
    }
    dpar[tid] = den;
    __syncthreads();
    if (blockIdx.y == 0 && tid < BI)
        pden[split * NN + rowbase + tid] = dpar[tid] + dpar[tid + 128];
}

// ---------------- fused D=64 attention: blockIdx.y selects layer ---------
__global__ __launch_bounds__(256, 2) void attn64f_kernel(
    const unsigned* __restrict__ ht0, const unsigned* __restrict__ ht1,
    const float4* __restrict__ rv0, const float4* __restrict__ cv0,
    const float4* __restrict__ rv1, const float4* __restrict__ cv1,
    const unsigned* __restrict__ adjbits,
    float* __restrict__ pacc,       // [2][8][NN][64]
    float* __restrict__ pden)       // [2][8][NN]
{
    constexpr int BI = 128, BJ = 32, BIp = 136, DC = 64, DCp = 72;
    constexpr int NT = 8;            // MT=1, ROWG=8, COLG=1
    constexpr int WS1 = BJ * BIp;
    constexpr int HS1 = BJ * DCp;
    constexpr int CP_IT = 2;         // 32*64/(4*256)

    extern __shared__ __align__(16) unsigned smem_u[];
    unsigned* Ws = smem_u;
    unsigned* hs = smem_u + 3 * WS1;
    float4*   cvs = (float4*)(smem_u + 3 * WS1 + 3 * HS1);
    float*    dpar = (float*)(smem_u + 3 * WS1 + 3 * HS1 + 384);

    const int tid = threadIdx.x;
    const int wid = tid >> 5, lane = tid & 31;
    const int grp = lane >> 2, tid4 = lane & 3;
    const int warpRow = wid;         // ROWG=8
    const int rowbase = blockIdx.x * BI;
    const int layer = blockIdx.y;
    const int split = blockIdx.z;
    const int jcnt = NN / gridDim.z;
    const int jbeg = split * jcnt;
    const int T = jcnt / BJ;

    const unsigned* ht = layer ? ht1 : ht0;
    const float4* rowvals = layer ? rv1 : rv0;
    const float4* colvals = layer ? cv1 : cv0;
    float* pacc_l = pacc + (size_t)layer * 8 * NN * DC;
    float* pden_l = pden + (size_t)layer * 8 * NN;

    const int iA = tid & 127;
    const int jAb = (tid >> 7) * 16;
    const float4 rv = rowvals[rowbase + iA];
    float den = 0.f;

    float acc[NT][4];
#pragma unroll
    for (int n = 0; n < NT; ++n)
#pragma unroll
        for (int q = 0; q < 4; ++q) acc[n][q] = 0.f;

    auto cp_tile = [&](int t, int buf) {
        const int j0 = jbeg + t * BJ;
        unsigned* hb = hs + buf * HS1;
#pragma unroll
        for (int it = 0; it < CP_IT; ++it) {
            int q = tid + it * 256;
            int row = q >> 4;
            int c = (q & 15) * 4;
            cp_async16(&hb[row * DCp + c], &ht[(size_t)(j0 + row) * DC + c]);
        }
        if (tid < 32) cp_async16(&cvs[buf * 32 + tid], &colvals[j0 + tid]);
    };
    auto phaseA = [&](int buf, unsigned mw) {
        unsigned* Wb = Ws + buf * WS1;
        const float4* cv = cvs + buf * 32;
        const unsigned msk = mw >> jAb;
#pragma unroll
        for (int e = 0; e < 16; ++e) {
            int j = jAb + e;
            float4 c = cv[j];
            bool p = c.x > rv.x;
            float w = p ? (rv.y * c.y) : (rv.z * c.z);
            w = ((msk >> e) & 1u) ? w : 0.f;
            den += w;
            Wb[j * BIp + iA] = f2tf(w);
        }
    };
    auto phaseB = [&](int buf) {
        const unsigned* Wb = Ws + buf * WS1;
        const unsigned* hb = hs + buf * HS1;
#pragma unroll
        for (int k0 = 0; k0 < BJ; k0 += 8) {
            unsigned afr[4];
            int rb = warpRow * 16;
            afr[0] = Wb[(k0 + tid4) * BIp + rb + grp];
            afr[1] = Wb[(k0 + tid4) * BIp + rb + grp + 8];
            afr[2] = Wb[(k0 + tid4 + 4) * BIp + rb + grp];
            afr[3] = Wb[(k0 + tid4 + 4) * BIp + rb + grp + 8];
#pragma unroll
            for (int n = 0; n < NT; ++n) {
                int n0 = n * 8;
                unsigned b0 = hb[(k0 + tid4) * DCp + n0 + grp];
                unsigned b1 = hb[(k0 + tid4 + 4) * DCp + n0 + grp];
                mma_tf32(acc[n], afr, b0, b1);
            }
        }
    };

    {
        cp_tile(0, 0);
        CP_COMMIT();
        unsigned mw = adjbits[(size_t)(rowbase + iA) * (NN / 32) + (jbeg >> 5)];
        CP_WAIT0();
        __syncthreads();
        phaseA(0, mw);
    }

    for (int t = 0; t < T; ++t) {
        const int cur = t % 3;
        const bool more = (t + 1 < T);
        unsigned mw = 0;
        if (more) {
            cp_tile(t + 1, (t + 1) % 3);
            CP_COMMIT();
            mw = adjbits[(size_t)(rowbase + iA) * (NN / 32) + ((jbeg + (t + 1) * BJ) >> 5)];
        }
        __syncthreads();
        phaseB(cur);
        if (more) {
            CP_WAIT0();
            __syncthreads();
            phaseA((t + 1) % 3, mw);
        }
    }

    {
        int r0 = rowbase + warpRow * 16 + grp;
#pragma unroll
        for (int n = 0; n < NT; ++n) {
            int col = n * 8 + 2 * tid4;
            float* p0 = pacc_l + ((size_t)split * NN + r0) * DC + col;
            float* p1 = pacc_l + ((size_t)split * NN + r0 + 8) * DC + col;
            *(float2*)p0 = make_float2(acc[n][0], acc[n][1]);
            *(float2*)p1 = make_float2(acc[n][2], acc[n][3]);
        }
    }
    dpar[tid] = den;
    __syncthreads();
    if (tid < BI)
        pden_l[split * NN + rowbase + tid] = dpar[tid] + dpar[tid + 128];
}

// ---------------- combine split partials + normalize (layer 0) -----------
__global__ void combine_kernel(const float* __restrict__ pacc, const float* __restrict__ pden,
                               float* __restrict__ out, int D, int nsplit)
{
    int idx = blockIdx.x * blockDim.x + threadIdx.x;
    int total = NN * D / 4;
    if (idx >= total) return;
    int row = idx / (D / 4);
    float4 s = make_float4(0.f, 0.f, 0.f, 0.f);
    float dd = 0.f;
    for (int sp = 0; sp < nsplit; ++sp) {
        float4 v = ((const float4*)pacc)[(size_t)sp * total + idx];
        s.x += v.x; s.y += v.y; s.z += v.z; s.w += v.w;
        dd += pden[sp * NN + row];
    }
    float inv = 1.f / dd;
    s.x *= inv; s.y *= inv; s.z *= inv; s.w *= inv;
    ((float4*)out)[idx] = s;
}

// ---------------- combine both D=64 layers + Z in one pass ---------------
__global__ void combine_z_kernel(const float* __restrict__ pacc, const float* __restrict__ pden,
                                 const float* __restrict__ noise, float* __restrict__ Z)
{
    int idx = blockIdx.x * blockDim.x + threadIdx.x;   // float4 index
    const int total = NN * DH2 / 4;
    if (idx >= total) return;
    int row = idx / (DH2 / 4);
    const float4* pm = (const float4*)pacc;
    const float4* pl = (const float4*)(pacc + (size_t)8 * NN * DH2);
    float4 m = make_float4(0.f, 0.f, 0.f, 0.f);
    float4 l = make_float4(0.f, 0.f, 0.f, 0.f);
    float dm = 0.f, dl = 0.f;
    for (int sp = 0; sp < 8; ++sp) {
        float4 v = pm[(size_t)sp * total + idx];
        m.x += v.x; m.y += v.y; m.z += v.z; m.w += v.w;
        float4 u = pl[(size_t)sp * total + idx];
        l.x += u.x; l.y += u.y; l.z += u.z; l.w += u.w;
        dm += pden[sp * NN + row];
        dl += pden[8 * NN + sp * NN + row];
    }
    float im = 1.f / dm, il = 1.f / dl;
    float4 nz = ((const float4*)noise)[idx];
    float4 z;
    z.x = nz.x * fast_exp(l.x * il) + m.x * im;
    z.y = nz.y * fast_exp(l.y * il) + m.y * im;
    z.z = nz.z * fast_exp(l.z * il) + m.z * im;
    z.w = nz.w * fast_exp(l.w * il) + m.w * im;
    ((float4*)Z)[idx] = z;
}

// ---------------- A = sigmoid(Z @ Z^T): tf32 mma, coalesced mirror -------
__global__ __launch_bounds__(256, 2) void zzt2_kernel(const float* __restrict__ Z,
                                                      float* __restrict__ out)
{
    const int bi = blockIdx.y, bj = blockIdx.x;
    if (bj < bi) return;
    extern __shared__ __align__(16) unsigned zs[];
    unsigned* Zi = zs;
    unsigned* Zj = zs + 128 * 68;
    const int tid = threadIdx.x, wid = tid >> 5, lane = tid & 31;
    const int grp = lane >> 2, tid4 = lane & 3;
    const int warpRow = wid & 3, warpCol = wid >> 2;
    const int i0 = bi * 128, j0 = bj * 128;

#pragma unroll
    for (int it = 0; it < 16; ++it) {
        int q = tid + it * 256;
        int tile = q >> 11;
        int qq = q & 2047;
        int r = qq >> 4, c4 = (qq & 15) * 4;
        int gr = (tile ? j0 : i0) + r;
        float4 v = *(const float4*)&Z[(size_t)gr * DH2 + c4];
        uint4 t;
        t.x = f2tf(v.x); t.y = f2tf(v.y); t.z = f2tf(v.z); t.w = f2tf(v.w);
        *(uint4*)&((tile ? Zj : Zi)[r * 68 + c4]) = t;
    }
    __syncthreads();

    float acc[2][8][4] = {};
#pragma unroll
    for (int kk = 0; kk < 8; ++kk) {
        int kb = kk * 8;
        unsigned af[2][4];
#pragma unroll
        for (int m = 0; m < 2; ++m) {
            int rb = (warpRow * 2 + m) * 16;
            af[m][0] = Zi[(rb + grp) * 68 + kb + tid4];
            af[m][1] = Zi[(rb + grp + 8) * 68 + kb + tid4];
            af[m][2] = Zi[(rb + grp) * 68 + kb + tid4 + 4];
            af[m][3] = Zi[(rb + grp + 8) * 68 + kb + tid4 + 4];
        }
#pragma unroll
        for (int n = 0; n < 8; ++n) {
            int nn = warpCol * 64 + n * 8;
            unsigned b0 = Zj[(nn + grp) * 68 + kb + tid4];
            unsigned b1 = Zj[(nn + grp) * 68 + kb + tid4 + 4];
#pragma unroll
            for (int m = 0; m < 2; ++m)
                mma_tf32(acc[m][n], af[m], b0, b1);
        }
    }

#pragma unroll
    for (int m = 0; m < 2; ++m) {
        int r0 = i0 + (warpRow * 2 + m) * 16 + grp;
#pragma unroll
        for (int n = 0; n < 8; ++n) {
            int col = j0 + warpCol * 64 + n * 8 + 2 * tid4;
#pragma unroll
            for (int q = 0; q < 4; ++q) acc[m][n][q] = fast_sigmoid(acc[m][n][q]);
            *(float2*)&out[(size_t)r0 * NN + col] = make_float2(acc[m][n][0], acc[m][n][1]);
            *(float2*)&out[(size_t)(r0 + 8) * NN + col] = make_float2(acc[m][n][2], acc[m][n][3]);
        }
    }

    if (bj > bi) {
        __syncthreads();
        float* sT = (float*)zs;
#pragma unroll
        for (int m = 0; m < 2; ++m) {
            int lr0 = (warpRow * 2 + m) * 16 + grp;
#pragma unroll
            for (int n = 0; n < 8; ++n) {
                int lc = warpCol * 64 + n * 8 + 2 * tid4;
                sT[(size_t)lc * 132 + lr0] = acc[m][n][0];
                sT[(size_t)(lc + 1) * 132 + lr0] = acc[m][n][1];
                sT[(size_t)lc * 132 + lr0 + 8] = acc[m][n][2];
                sT[(size_t)(lc + 1) * 132 + lr0 + 8] = acc[m][n][3];
            }
        }
        __syncthreads();
#pragma unroll
        for (int it = 0; it < 16; ++it) {
            int q = tid + it * 256;
            int rr = q >> 5, cc = (q & 31) * 4;
            float4 v = *(float4*)&sT[(size_t)rr * 132 + cc];
            *(float4*)&out[(size_t)(j0 + rr) * NN + i0 + cc] = v;
        }
    }
}

// ---------------- host orchestration -------------------------------------
extern "C" void kernel_launch(void* const* d_in, const int* in_sizes, int n_in,
                              void* d_out, int out_size)
{
    const float* X     = (const float*)d_in[0];
    const int*   adj   = (const int*)  d_in[1];
    const float* noise = (const float*)d_in[2];
    const float* W0    = (const float*)d_in[3];
    const float* a0    = (const float*)d_in[4];
    const float* W1    = (const float*)d_in[5];
    const float* a1    = (const float*)d_in[6];
    const float* W2    = (const float*)d_in[7];
    const float* a2    = (const float*)d_in[8];
    float* out = (float*)d_out;

    float *p_h0, *p_hidden, *p_h1, *p_h2, *p_Z, *p_pacc, *p_pden;
    unsigned *p_h0t, *p_h1t, *p_h2t;
    float4 *p_rv, *p_cv, *p_rv2, *p_cv2;
    unsigned* p_bits;
    cudaGetSymbolAddress((void**)&p_h0, g_h0);
    cudaGetSymbolAddress((void**)&p_h0t, g_h0t);
    cudaGetSymbolAddress((void**)&p_hidden, g_hidden);
    cudaGetSymbolAddress((void**)&p_h1, g_h1);
    cudaGetSymbolAddress((void**)&p_h1t, g_h1t);
    cudaGetSymbolAddress((void**)&p_h2, g_h2);
    cudaGetSymbolAddress((void**)&p_h2t, g_h2t);
    cudaGetSymbolAddress((void**)&p_Z, g_Z);
    cudaGetSymbolAddress((void**)&p_pacc, g_pacc);
    cudaGetSymbolAddress((void**)&p_pden, g_pden);
    cudaGetSymbolAddress((void**)&p_rv, g_rowvals);
    cudaGetSymbolAddress((void**)&p_cv, g_colvals);
    cudaGetSymbolAddress((void**)&p_rv2, g_rowvals2);
    cudaGetSymbolAddress((void**)&p_cv2, g_colvals2);
    cudaGetSymbolAddress((void**)&p_bits, g_adjbits);

    const int smem256 = (3 * 32 * 136 + 3 * 32 * 136 + 384 + 256) * 4;  // 107008
    const int smem64  = (3 * 32 * 136 + 3 * 32 * 72 + 384 + 256) * 4;   // 82432
    const int smemZZ  = 2 * 128 * 68 * 4;                               // 69632
    cudaFuncSetAttribute((const void*)attn9_kernel<DH1, 128, 2, 4, 2>,
                         cudaFuncAttributeMaxDynamicSharedMemorySize, smem256);
    cudaFuncSetAttribute((const void*)attn64f_kernel,
                         cudaFuncAttributeMaxDynamicSharedMemorySize, smem64);
    cudaFuncSetAttribute((const void*)zzt2_kernel,
                         cudaFuncAttributeMaxDynamicSharedMemorySize, smemZZ);

    pack_adj_kernel<<<NN * NN / 256, 256>>>(adj, p_bits);

    // ---- layer 0 ----
    gemmtf_kernel<DIN><<<dim3(NN / 128, DH1 / 64), 256>>>(X, W0, p_h0, p_h0t, DH1);
    vals_kernel<<<NN / 8, 256>>>(p_h0, a0, DH1, p_rv, p_cv);
    attn9_kernel<DH1, 128, 2, 4, 2><<<dim3(NN / 128, 2, 8), 256, smem256>>>(p_h0t, p_rv, p_cv, p_bits, p_pacc, p_pden);
    combine_kernel<<<NN * DH1 / 4 / 256, 256>>>(p_pacc, p_pden, p_hidden, DH1, 8);

    // ---- layers 1+2 fused ----
    gemmtf_kernel<DH1><<<dim3(NN / 128, 1), 256>>>(p_hidden, W1, p_h1, p_h1t, DH2);
    gemmtf_kernel<DH1><<<dim3(NN / 128, 1), 256>>>(p_hidden, W2, p_h2, p_h2t, DH2);
    vals_kernel<<<NN / 8, 256>>>(p_h1, a1, DH2, p_rv, p_cv);
    vals_kernel<<<NN / 8, 256>>>(p_h2, a2, DH2, p_rv2, p_cv2);
    attn64f_kernel<<<dim3(NN / 128, 2, 8), 256, smem64>>>(p_h1t, p_h2t, p_rv, p_cv, p_rv2, p_cv2, p_bits, p_pacc, p_pden);
    combine_z_kernel<<<NN * DH2 / 4 / 256, 256>>>(p_pacc, p_pden, noise, p_Z);

    // ---- decoder ----
    zzt2_kernel<<<dim3(NN / 128, NN / 128), 256, smemZZ>>>(p_Z, out);
}

// round 13
// speedup vs baseline: 1.4904x; 1.1222x over previous
#include <cuda_runtime.h>
#include <cuda_bf16.h>

#define NN 4096
#define DIN 512
#define DH1 256
#define DH2 64
#define ALPHA 0.2f

__device__ __forceinline__ unsigned f2tf(float f) {
    unsigned u; asm("cvt.rna.tf32.f32 %0, %1;" : "=r"(u) : "f"(f)); return u;
}
__device__ __forceinline__ void mma_tf32(float* c, const unsigned* a, unsigned b0, unsigned b1) {
    asm volatile("mma.sync.aligned.m16n8k8.row.col.f32.tf32.tf32.f32 "
                 "{%0,%1,%2,%3}, {%4,%5,%6,%7}, {%8,%9}, {%0,%1,%2,%3};"
                 : "+f"(c[0]), "+f"(c[1]), "+f"(c[2]), "+f"(c[3])
                 : "r"(a[0]), "r"(a[1]), "r"(a[2]), "r"(a[3]), "r"(b0), "r"(b1));
}
__device__ __forceinline__ void cp_async16(void* dst_smem, const void* src) {
    unsigned d = (unsigned)__cvta_generic_to_shared(dst_smem);
    asm volatile("cp.async.cg.shared.global [%0], [%1], 16;" :: "r"(d), "l"(src));
}
#define CP_COMMIT() asm volatile("cp.async.commit_group;")
#define CP_WAIT0()  asm volatile("cp.async.wait_group 0;")
#define CP_WAIT1()  asm volatile("cp.async.wait_group 1;")

// fma/alu-only exp2-based exp and sigmoid
__device__ __forceinline__ float fast_exp(float x) {
    float u = x * 1.44269504f;
    u = fminf(fmaxf(u, -60.f), 60.f);
    float s = u + 12582912.f;
    int n = __float_as_int(s) - 0x4B400000;
    float f = u - (s - 12582912.f);
    float p = 0.00133336f;
    p = fmaf(p, f, 0.00961813f);
    p = fmaf(p, f, 0.05550411f);
    p = fmaf(p, f, 0.24022651f);
    p = fmaf(p, f, 0.69314718f);
    p = fmaf(p, f, 1.0f);
    return __int_as_float(__float_as_int(p) + (n << 23));
}
__device__ __forceinline__ float fast_sigmoid(float x) {
    float e = fast_exp(-x);
    float d = 1.f + e;
    float y = __int_as_float(0x7EF311C3 - __float_as_int(d));
    y = y * fmaf(-d, y, 2.f);
    y = y * fmaf(-d, y, 2.f);
    return y;
}

// ---------------- device scratch (no allocations allowed) ----------------
__device__ float    g_h0[NN * DH1];
__device__ unsigned g_h0t[NN * DH1];
__device__ float    g_hidden[NN * DH1];
__device__ float    g_h1[NN * DH2];
__device__ unsigned g_h1t[NN * DH2];
__device__ float    g_h2[NN * DH2];
__device__ unsigned g_h2t[NN * DH2];
__device__ float    g_Z[NN * DH2];
__device__ float4   g_rowvals[NN];
__device__ float4   g_colvals[NN];
__device__ float4   g_rowvals2[NN];
__device__ float4   g_colvals2[NN];
__device__ unsigned g_adjbits[NN * (NN / 32)];
__device__ float    g_pacc[8 * NN * DH1];    // layer0: 8 splits x N x 256 (exact)
__device__ float    g_pden[16 * NN];

// ---------------- pack adjacency into bitmask ----------------------------
__global__ void pack_adj_kernel(const int* __restrict__ adj, unsigned* __restrict__ bits) {
    int idx = blockIdx.x * 256 + threadIdx.x;
    unsigned b = __ballot_sync(0xffffffffu, adj[idx] > 0);
    if ((threadIdx.x & 31) == 0) bits[idx >> 5] = b;
}

// ---------------- tf32 mma GEMM with dual (fp32 + tf32) output -----------
template<int K>
__global__ __launch_bounds__(256) void gemmtf_kernel(
    const float* __restrict__ A, const float* __restrict__ B,
    float* __restrict__ C, unsigned* __restrict__ Ct, int N)
{
    __shared__ __align__(16) unsigned As[128 * 36];
    __shared__ __align__(16) unsigned Bs[32 * 68];
    const int tid = threadIdx.x, wid = tid >> 5, lane = tid & 31;
    const int grp = lane >> 2, tid4 = lane & 3;
    const int warpRow = wid & 3, warpCol = wid >> 2;
    const int m0 = blockIdx.x * 128, n0 = blockIdx.y * 64;

    float acc[2][4][4] = {};
    for (int k0 = 0; k0 < K; k0 += 32) {
        __syncthreads();
#pragma unroll
        for (int it = 0; it < 4; ++it) {
            int q = tid + it * 256;
            int r = q >> 3, c4 = (q & 7) * 4;
            float4 v = *(const float4*)&A[(size_t)(m0 + r) * K + k0 + c4];
            uint4 t;
            t.x = f2tf(v.x); t.y = f2tf(v.y); t.z = f2tf(v.z); t.w = f2tf(v.w);
            *(uint4*)&As[r * 36 + c4] = t;
        }
#pragma unroll
        for (int it = 0; it < 2; ++it) {
            int q = tid + it * 256;
            int r = q >> 4, c4 = (q & 15) * 4;
            float4 v = *(const float4*)&B[(size_t)(k0 + r) * N + n0 + c4];
            uint4 t;
            t.x = f2tf(v.x); t.y = f2tf(v.y); t.z = f2tf(v.z); t.w = f2tf(v.w);
            *(uint4*)&Bs[r * 68 + c4] = t;
        }
        __syncthreads();
#pragma unroll
        for (int kk = 0; kk < 4; ++kk) {
            int kb = kk * 8;
            unsigned af[2][4];
#pragma unroll
            for (int m = 0; m < 2; ++m) {
                int rb = (warpRow * 2 + m) * 16;
                af[m][0] = As[(rb + grp) * 36 + kb + tid4];
                af[m][1] = As[(rb + grp + 8) * 36 + kb + tid4];
                af[m][2] = As[(rb + grp) * 36 + kb + tid4 + 4];
                af[m][3] = As[(rb + grp + 8) * 36 + kb + tid4 + 4];
            }
#pragma unroll
            for (int n = 0; n < 4; ++n) {
                int nn = warpCol * 32 + n * 8;
                unsigned b0 = Bs[(kb + tid4) * 68 + nn + grp];
                unsigned b1 = Bs[(kb + tid4 + 4) * 68 + nn + grp];
                mma_tf32(acc[0][n], af[0], b0, b1);
                mma_tf32(acc[1][n], af[1], b0, b1);
            }
        }
    }
#pragma unroll
    for (int m = 0; m < 2; ++m) {
        int r0 = m0 + (warpRow * 2 + m) * 16 + grp;
#pragma unroll
        for (int n = 0; n < 4; ++n) {
            int col = n0 + warpCol * 32 + n * 8 + 2 * tid4;
            float a0 = acc[m][n][0], a1 = acc[m][n][1];
            float a2 = acc[m][n][2], a3 = acc[m][n][3];
            *(float2*)&C[(size_t)r0 * N + col] = make_float2(a0, a1);
            *(float2*)&C[(size_t)(r0 + 8) * N + col] = make_float2(a2, a3);
            *(uint2*)&Ct[(size_t)r0 * N + col] = make_uint2(f2tf(a0), f2tf(a1));
            *(uint2*)&Ct[(size_t)(r0 + 8) * N + col] = make_uint2(f2tf(a2), f2tf(a3));
        }
    }
}

// ---------------- per-row attention scalars ------------------------------
__global__ void vals_kernel(const float* __restrict__ h, const float* __restrict__ a,
                            int D, float4* __restrict__ rowvals, float4* __restrict__ colvals)
{
    int warp = (blockIdx.x * blockDim.x + threadIdx.x) >> 5;
    int lane = threadIdx.x & 31;
    if (warp >= NN) return;
    float s1 = 0.f, s2 = 0.f;
    for (int d = lane; d < D; d += 32) {
        float hv = h[(size_t)warp * D + d];
        s1 += hv * a[d];
        s2 += hv * a[D + d];
    }
#pragma unroll
    for (int o = 16; o; o >>= 1) {
        s1 += __shfl_xor_sync(0xffffffffu, s1, o);
        s2 += __shfl_xor_sync(0xffffffffu, s2, o);
    }
    if (lane == 0) {
        rowvals[warp] = make_float4(-s1, expf(s1), expf(ALPHA * s1), 0.f);
        colvals[warp] = make_float4(s2, expf(s2), expf(ALPHA * s2), 0.f);
    }
}

// ---------------- attention vR: weights-in-registers, 1 barrier/tile -----
// A-fragment weights computed per-thread into registers (no Ws smem tile).
// 3-ring hs/cvs via cp.async; single __syncthreads per tile.
template<int D, int DC, int MT, int ROWG, int COLG, int MAXB>
__global__ __launch_bounds__(256, MAXB) void attnR_kernel(
    const unsigned* __restrict__ ht,
    const float4* __restrict__ rowvals,
    const float4* __restrict__ colvals,
    const unsigned* __restrict__ adjbits,
    float* __restrict__ pacc,
    float* __restrict__ pden)
{
    constexpr int BI = 128, BJ = 32;
    constexpr int DCp = DC + 8;
    constexpr int NT = DC / (COLG * 8);
    constexpr int HS1 = BJ * DCp;
    constexpr int CP_IT = BJ * DC / (4 * 256);

    extern __shared__ __align__(16) unsigned smem_u[];
    unsigned* hs = smem_u;                         // [3][HS1]
    float4*   cvs = (float4*)(smem_u + 3 * HS1);   // [3][32]

    const int tid = threadIdx.x;
    const int wid = tid >> 5, lane = tid & 31;
    const int grp = lane >> 2, tid4 = lane & 3;
    const int warpRow = wid % ROWG, warpCol = wid / ROWG;
    const int rowbase = blockIdx.x * BI;
    const int colbase = blockIdx.y * DC;
    const int split = blockIdx.z;
    const int jcnt = NN / gridDim.z;
    const int jbeg = split * jcnt;
    const int T = jcnt / BJ;

    // per-thread rows + rowvals (fixed for whole kernel)
    int ra[MT];
    float4 rva[MT], rvb[MT];
#pragma unroll
    for (int m = 0; m < MT; ++m) {
        ra[m] = rowbase + (warpRow * MT + m) * 16 + grp;
        rva[m] = rowvals[ra[m]];
        rvb[m] = rowvals[ra[m] + 8];
    }

    float acc[MT][NT][4];
#pragma unroll
    for (int m = 0; m < MT; ++m)
#pragma unroll
        for (int n = 0; n < NT; ++n)
#pragma unroll
            for (int q = 0; q < 4; ++q) acc[m][n][q] = 0.f;
    float denA[MT], denB[MT];
#pragma unroll
    for (int m = 0; m < MT; ++m) { denA[m] = 0.f; denB[m] = 0.f; }

    auto cp_tile = [&](int t, int buf) {
        const int j0 = jbeg + t * BJ;
        unsigned* hb = hs + buf * HS1;
#pragma unroll
        for (int it = 0; it < CP_IT; ++it) {
            int q = tid + it * 256;
            int row = q / (DC / 4);
            int c = (q % (DC / 4)) * 4;
            cp_async16(&hb[row * DCp + c], &ht[(size_t)(j0 + row) * D + colbase + c]);
        }
        if (tid < 32) cp_async16(&cvs[buf * 32 + tid], &colvals[j0 + tid]);
    };

    auto phase = [&](int buf, const unsigned* ma, const unsigned* mb) {
        const float4* cv = cvs + buf * 32;
        const unsigned* hb = hs + buf * HS1;
#pragma unroll
        for (int k0 = 0; k0 < BJ; k0 += 8) {
            const int j1 = k0 + tid4, j2 = j1 + 4;
            float4 c1 = cv[j1];
            float4 c2 = cv[j2];
            unsigned afr[MT][4];
#pragma unroll
            for (int m = 0; m < MT; ++m) {
                float w0 = (c1.x > rva[m].x) ? (rva[m].y * c1.y) : (rva[m].z * c1.z);
                float w1 = (c1.x > rvb[m].x) ? (rvb[m].y * c1.y) : (rvb[m].z * c1.z);
                float w2 = (c2.x > rva[m].x) ? (rva[m].y * c2.y) : (rva[m].z * c2.z);
                float w3 = (c2.x > rvb[m].x) ? (rvb[m].y * c2.y) : (rvb[m].z * c2.z);
                w0 = ((ma[m] >> j1) & 1u) ? w0 : 0.f;
                w1 = ((mb[m] >> j1) & 1u) ? w1 : 0.f;
                w2 = ((ma[m] >> j2) & 1u) ? w2 : 0.f;
                w3 = ((mb[m] >> j2) & 1u) ? w3 : 0.f;
                denA[m] += w0 + w2;
                denB[m] += w1 + w3;
                afr[m][0] = f2tf(w0); afr[m][1] = f2tf(w1);
                afr[m][2] = f2tf(w2); afr[m][3] = f2tf(w3);
            }
#pragma unroll
            for (int n = 0; n < NT; ++n) {
                int n0 = warpCol * (NT * 8) + n * 8;
                unsigned b0 = hb[(k0 + tid4) * DCp + n0 + grp];
                unsigned b1 = hb[(k0 + tid4 + 4) * DCp + n0 + grp];
#pragma unroll
                for (int m = 0; m < MT; ++m)
                    mma_tf32(acc[m][n], afr[m], b0, b1);
            }
        }
    };

    // prologue: tile 0 copies + tile 0 masks
    unsigned ma[MT], mb[MT], ma_n[MT], mb_n[MT];
    cp_tile(0, 0);
    CP_COMMIT();
    {
        const int w0 = jbeg >> 5;
#pragma unroll
        for (int m = 0; m < MT; ++m) {
            ma[m] = adjbits[(size_t)ra[m] * (NN / 32) + w0];
            mb[m] = adjbits[(size_t)(ra[m] + 8) * (NN / 32) + w0];
        }
    }

    for (int t = 0; t < T; ++t) {
        const bool more = (t + 1 < T);
        if (more) {
            cp_tile(t + 1, (t + 1) % 3);
            CP_COMMIT();
            const int wN = (jbeg + (t + 1) * BJ) >> 5;
#pragma unroll
            for (int m = 0; m < MT; ++m) {
                ma_n[m] = adjbits[(size_t)ra[m] * (NN / 32) + wN];
                mb_n[m] = adjbits[(size_t)(ra[m] + 8) * (NN / 32) + wN];
            }
            CP_WAIT1();              // tile t's group complete (t+1 in flight)
        } else {
            CP_WAIT0();
        }
        __syncthreads();             // tile t data visible; phaseB(t-2) fenced for ring reuse
        phase(t % 3, ma, mb);
#pragma unroll
        for (int m = 0; m < MT; ++m) { ma[m] = ma_n[m]; mb[m] = mb_n[m]; }
    }

    // epilogue: accumulators
#pragma unroll
    for (int m = 0; m < MT; ++m) {
#pragma unroll
        for (int n = 0; n < NT; ++n) {
            int col = colbase + warpCol * (NT * 8) + n * 8 + 2 * tid4;
            float* p0 = pacc + ((size_t)split * NN + ra[m]) * D + col;
            float* p1 = pacc + ((size_t)split * NN + ra[m] + 8) * D + col;
            *(float2*)p0 = make_float2(acc[m][n][0], acc[m][n][1]);
            *(float2*)p1 = make_float2(acc[m][n][2], acc[m][n][3]);
        }
    }
    // denominators: reduce over tid4 group (lanes xor 1, 2), write once
    if (warpCol == 0 && blockIdx.y == 0) {
#pragma unroll
        for (int m = 0; m < MT; ++m) {
            float da = denA[m], db = denB[m];
            da += __shfl_xor_sync(0xffffffffu, da, 1);
            da += __shfl_xor_sync(0xffffffffu, da, 2);
            db += __shfl_xor_sync(0xffffffffu, db, 1);
            db += __shfl_xor_sync(0xffffffffu, db, 2);
            if (tid4 == 0) {
                pden[split * NN + ra[m]] = da;
                pden[split * NN + ra[m] + 8] = db;
            }
        }
    }
}

// ---------------- fused D=64 attention (register weights) ----------------
__global__ __launch_bounds__(256, 3) void attn64R_kernel(
    const unsigned* __restrict__ ht0, const unsigned* __restrict__ ht1,
    const float4* __restrict__ rv0, const float4* __restrict__ cv0,
    const float4* __restrict__ rv1, const float4* __restrict__ cv1,
    const unsigned* __restrict__ adjbits,
    float* __restrict__ pacc,       // [2][8][NN][64]
    float* __restrict__ pden)       // [2][8][NN]
{
    constexpr int BI = 128, BJ = 32, DC = 64, DCp = 72;
    constexpr int NT = 8;
    constexpr int HS1 = BJ * DCp;
    constexpr int CP_IT = 2;

    extern __shared__ __align__(16) unsigned smem_u[];
    unsigned* hs = smem_u;
    float4*   cvs = (float4*)(smem_u + 3 * HS1);

    const int tid = threadIdx.x;
    const int wid = tid >> 5, lane = tid & 31;
    const int grp = lane >> 2, tid4 = lane & 3;
    const int rowbase = blockIdx.x * BI;
    const int layer = blockIdx.y;
    const int split = blockIdx.z;
    const int jcnt = NN / gridDim.z;
    const int jbeg = split * jcnt;
    const int T = jcnt / BJ;

    const unsigned* ht = layer ? ht1 : ht0;
    const float4* rowvals = layer ? rv1 : rv0;
    const float4* colvals = layer ? cv1 : cv0;
    float* pacc_l = pacc + (size_t)layer * 8 * NN * DC;
    float* pden_l = pden + (size_t)layer * 8 * NN;

    const int ra = rowbase + wid * 16 + grp;
    const float4 rva = rowvals[ra];
    const float4 rvb = rowvals[ra + 8];

    float acc[NT][4];
#pragma unroll
    for (int n = 0; n < NT; ++n)
#pragma unroll
        for (int q = 0; q < 4; ++q) acc[n][q] = 0.f;
    float denA = 0.f, denB = 0.f;

    auto cp_tile = [&](int t, int buf) {
        const int j0 = jbeg + t * BJ;
        unsigned* hb = hs + buf * HS1;
#pragma unroll
        for (int it = 0; it < CP_IT; ++it) {
            int q = tid + it * 256;
            int row = q >> 4;
            int c = (q & 15) * 4;
            cp_async16(&hb[row * DCp + c], &ht[(size_t)(j0 + row) * DC + c]);
        }
        if (tid < 32) cp_async16(&cvs[buf * 32 + tid], &colvals[j0 + tid]);
    };

    auto phase = [&](int buf, unsigned ma, unsigned mb) {
        const float4* cv = cvs + buf * 32;
        const unsigned* hb = hs + buf * HS1;
#pragma unroll
        for (int k0 = 0; k0 < BJ; k0 += 8) {
            const int j1 = k0 + tid4, j2 = j1 + 4;
            float4 c1 = cv[j1];
            float4 c2 = cv[j2];
            float w0 = (c1.x > rva.x) ? (rva.y * c1.y) : (rva.z * c1.z);
            float w1 = (c1.x > rvb.x) ? (rvb.y * c1.y) : (rvb.z * c1.z);
            float w2 = (c2.x > rva.x) ? (rva.y * c2.y) : (rva.z * c2.z);
            float w3 = (c2.x > rvb.x) ? (rvb.y * c2.y) : (rvb.z * c2.z);
            w0 = ((ma >> j1) & 1u) ? w0 : 0.f;
            w1 = ((mb >> j1) & 1u) ? w1 : 0.f;
            w2 = ((ma >> j2) & 1u) ? w2 : 0.f;
            w3 = ((mb >> j2) & 1u) ? w3 : 0.f;
            denA += w0 + w2;
            denB += w1 + w3;
            unsigned afr[4];
            afr[0] = f2tf(w0); afr[1] = f2tf(w1);
            afr[2] = f2tf(w2); afr[3] = f2tf(w3);
#pragma unroll
            for (int n = 0; n < NT; ++n) {
                int n0 = n * 8;
                unsigned b0 = hb[(k0 + tid4) * DCp + n0 + grp];
                unsigned b1 = hb[(k0 + tid4 + 4) * DCp + n0 + grp];
                mma_tf32(acc[n], afr, b0, b1);
            }
        }
    };

    unsigned ma, mb, ma_n = 0, mb_n = 0;
    cp_tile(0, 0);
    CP_COMMIT();
    {
        const int w0 = jbeg >> 5;
        ma = adjbits[(size_t)ra * (NN / 32) + w0];
        mb = adjbits[(size_t)(ra + 8) * (NN / 32) + w0];
    }

    for (int t = 0; t < T; ++t) {
        const bool more = (t + 1 < T);
        if (more) {
            cp_tile(t + 1, (t + 1) % 3);
            CP_COMMIT();
            const int wN = (jbeg + (t + 1) * BJ) >> 5;
            ma_n = adjbits[(size_t)ra * (NN / 32) + wN];
            mb_n = adjbits[(size_t)(ra + 8) * (NN / 32) + wN];
            CP_WAIT1();
        } else {
            CP_WAIT0();
        }
        __syncthreads();
        phase(t % 3, ma, mb);
        ma = ma_n; mb = mb_n;
    }

#pragma unroll
    for (int n = 0; n < NT; ++n) {
        int col = n * 8 + 2 * tid4;
        float* p0 = pacc_l + ((size_t)split * NN + ra) * DC + col;
        float* p1 = pacc_l + ((size_t)split * NN + ra + 8) * DC + col;
        *(float2*)p0 = make_float2(acc[n][0], acc[n][1]);
        *(float2*)p1 = make_float2(acc[n][2], acc[n][3]);
    }
    {
        float da = denA, db = denB;
        da += __shfl_xor_sync(0xffffffffu, da, 1);
        da += __shfl_xor_sync(0xffffffffu, da, 2);
        db += __shfl_xor_sync(0xffffffffu, db, 1);
        db += __shfl_xor_sync(0xffffffffu, db, 2);
        if (tid4 == 0) {
            pden_l[split * NN + ra] = da;
            pden_l[split * NN + ra + 8] = db;
        }
    }
}

// ---------------- combine split partials + normalize (layer 0) -----------
__global__ void combine_kernel(const float* __restrict__ pacc, const float* __restrict__ pden,
                               float* __restrict__ out, int D, int nsplit)
{
    int idx = blockIdx.x * blockDim.x + threadIdx.x;
    int total = NN * D / 4;
    if (idx >= total) return;
    int row = idx / (D / 4);
    float4 s = make_float4(0.f, 0.f, 0.f, 0.f);
    float dd = 0.f;
    for (int sp = 0; sp < nsplit; ++sp) {
        float4 v = ((const float4*)pacc)[(size_t)sp * total + idx];
        s.x += v.x; s.y += v.y; s.z += v.z; s.w += v.w;
        dd += pden[sp * NN + row];
    }
    float inv = 1.f / dd;
    s.x *= inv; s.y *= inv; s.z *= inv; s.w *= inv;
    ((float4*)out)[idx] = s;
}

// ---------------- combine both D=64 layers + Z in one pass ---------------
__global__ void combine_z_kernel(const float* __restrict__ pacc, const float* __restrict__ pden,
                                 const float* __restrict__ noise, float* __restrict__ Z)
{
    int idx = blockIdx.x * blockDim.x + threadIdx.x;
    const int total = NN * DH2 / 4;
    if (idx >= total) return;
    int row = idx / (DH2 / 4);
    const float4* pm = (const float4*)pacc;
    const float4* pl = (const float4*)(pacc + (size_t)8 * NN * DH2);
    float4 m = make_float4(0.f, 0.f, 0.f, 0.f);
    float4 l = make_float4(0.f, 0.f, 0.f, 0.f);
    float dm = 0.f, dl = 0.f;
    for (int sp = 0; sp < 8; ++sp) {
        float4 v = pm[(size_t)sp * total + idx];
        m.x += v.x; m.y += v.y; m.z += v.z; m.w += v.w;
        float4 u = pl[(size_t)sp * total + idx];
        l.x += u.x; l.y += u.y; l.z += u.z; l.w += u.w;
        dm += pden[sp * NN + row];
        dl += pden[8 * NN + sp * NN + row];
    }
    float im = 1.f / dm, il = 1.f / dl;
    float4 nz = ((const float4*)noise)[idx];
    float4 z;
    z.x = nz.x * fast_exp(l.x * il) + m.x * im;
    z.y = nz.y * fast_exp(l.y * il) + m.y * im;
    z.z = nz.z * fast_exp(l.z * il) + m.z * im;
    z.w = nz.w * fast_exp(l.w * il) + m.w * im;
    ((float4*)Z)[idx] = z;
}

// ---------------- A = sigmoid(Z @ Z^T): tf32 mma, coalesced mirror -------
__global__ __launch_bounds__(256, 2) void zzt2_kernel(const float* __restrict__ Z,
                                                      float* __restrict__ out)
{
    const int bi = blockIdx.y, bj = blockIdx.x;
    if (bj < bi) return;
    extern __shared__ __align__(16) unsigned zs[];
    unsigned* Zi = zs;
    unsigned* Zj = zs + 128 * 68;
    const int tid = threadIdx.x, wid = tid >> 5, lane = tid & 31;
    const int grp = lane >> 2, tid4 = lane & 3;
    const int warpRow = wid & 3, warpCol = wid >> 2;
    const int i0 = bi * 128, j0 = bj * 128;

#pragma unroll
    for (int it = 0; it < 16; ++it) {
        int q = tid + it * 256;
        int tile = q >> 11;
        int qq = q & 2047;
        int r = qq >> 4, c4 = (qq & 15) * 4;
        int gr = (tile ? j0 : i0) + r;
        float4 v = *(const float4*)&Z[(size_t)gr * DH2 + c4];
        uint4 t;
        t.x = f2tf(v.x); t.y = f2tf(v.y); t.z = f2tf(v.z); t.w = f2tf(v.w);
        *(uint4*)&((tile ? Zj : Zi)[r * 68 + c4]) = t;
    }
    __syncthreads();

    float acc[2][8][4] = {};
#pragma unroll
    for (int kk = 0; kk < 8; ++kk) {
        int kb = kk * 8;
        unsigned af[2][4];
#pragma unroll
        for (int m = 0; m < 2; ++m) {
            int rb = (warpRow * 2 + m) * 16;
            af[m][0] = Zi[(rb + grp) * 68 + kb + tid4];
            af[m][1] = Zi[(rb + grp + 8) * 68 + kb + tid4];
            af[m][2] = Zi[(rb + grp) * 68 + kb + tid4 + 4];
            af[m][3] = Zi[(rb + grp + 8) * 68 + kb + tid4 + 4];
        }
#pragma unroll
        for (int n = 0; n < 8; ++n) {
            int nn = warpCol * 64 + n * 8;
            unsigned b0 = Zj[(nn + grp) * 68 + kb + tid4];
            unsigned b1 = Zj[(nn + grp) * 68 + kb + tid4 + 4];
#pragma unroll
            for (int m = 0; m < 2; ++m)
                mma_tf32(acc[m][n], af[m], b0, b1);
        }
    }

#pragma unroll
    for (int m = 0; m < 2; ++m) {
        int r0 = i0 + (warpRow * 2 + m) * 16 + grp;
#pragma unroll
        for (int n = 0; n < 8; ++n) {
            int col = j0 + warpCol * 64 + n * 8 + 2 * tid4;
#pragma unroll
            for (int q = 0; q < 4; ++q) acc[m][n][q] = fast_sigmoid(acc[m][n][q]);
            *(float2*)&out[(size_t)r0 * NN + col] = make_float2(acc[m][n][0], acc[m][n][1]);
            *(float2*)&out[(size_t)(r0 + 8) * NN + col] = make_float2(acc[m][n][2], acc[m][n][3]);
        }
    }

    if (bj > bi) {
        __syncthreads();
        float* sT = (float*)zs;
#pragma unroll
        for (int m = 0; m < 2; ++m) {
            int lr0 = (warpRow * 2 + m) * 16 + grp;
#pragma unroll
            for (int n = 0; n < 8; ++n) {
                int lc = warpCol * 64 + n * 8 + 2 * tid4;
                sT[(size_t)lc * 132 + lr0] = acc[m][n][0];
                sT[(size_t)(lc + 1) * 132 + lr0] = acc[m][n][1];
                sT[(size_t)lc * 132 + lr0 + 8] = acc[m][n][2];
                sT[(size_t)(lc + 1) * 132 + lr0 + 8] = acc[m][n][3];
            }
        }
        __syncthreads();
#pragma unroll
        for (int it = 0; it < 16; ++it) {
            int q = tid + it * 256;
            int rr = q >> 5, cc = (q & 31) * 4;
            float4 v = *(float4*)&sT[(size_t)rr * 132 + cc];
            *(float4*)&out[(size_t)(j0 + rr) * NN + i0 + cc] = v;
        }
    }
}

// ---------------- host orchestration -------------------------------------
extern "C" void kernel_launch(void* const* d_in, const int* in_sizes, int n_in,
                              void* d_out, int out_size)
{
    const float* X     = (const float*)d_in[0];
    const int*   adj   = (const int*)  d_in[1];
    const float* noise = (const float*)d_in[2];
    const float* W0    = (const float*)d_in[3];
    const float* a0    = (const float*)d_in[4];
    const float* W1    = (const float*)d_in[5];
    const float* a1    = (const float*)d_in[6];
    const float* W2    = (const float*)d_in[7];
    const float* a2    = (const float*)d_in[8];
    float* out = (float*)d_out;

    float *p_h0, *p_hidden, *p_h1, *p_h2, *p_Z, *p_pacc, *p_pden;
    unsigned *p_h0t, *p_h1t, *p_h2t;
    float4 *p_rv, *p_cv, *p_rv2, *p_cv2;
    unsigned* p_bits;
    cudaGetSymbolAddress((void**)&p_h0, g_h0);
    cudaGetSymbolAddress((void**)&p_h0t, g_h0t);
    cudaGetSymbolAddress((void**)&p_hidden, g_hidden);
    cudaGetSymbolAddress((void**)&p_h1, g_h1);
    cudaGetSymbolAddress((void**)&p_h1t, g_h1t);
    cudaGetSymbolAddress((void**)&p_h2, g_h2);
    cudaGetSymbolAddress((void**)&p_h2t, g_h2t);
    cudaGetSymbolAddress((void**)&p_Z, g_Z);
    cudaGetSymbolAddress((void**)&p_pacc, g_pacc);
    cudaGetSymbolAddress((void**)&p_pden, g_pden);
    cudaGetSymbolAddress((void**)&p_rv, g_rowvals);
    cudaGetSymbolAddress((void**)&p_cv, g_colvals);
    cudaGetSymbolAddress((void**)&p_rv2, g_rowvals2);
    cudaGetSymbolAddress((void**)&p_cv2, g_colvals2);
    cudaGetSymbolAddress((void**)&p_bits, g_adjbits);

    // smem: 3 * hs(32*(DC+8)) words + cvs(3*32*16B)
    const int smem256 = (3 * 32 * 136) * 4 + 3 * 32 * 16;   // 53760
    const int smem64  = (3 * 32 * 72) * 4 + 3 * 32 * 16;    // 29184
    const int smemZZ  = 2 * 128 * 68 * 4;                   // 69632
    cudaFuncSetAttribute((const void*)attnR_kernel<DH1, 128, 2, 4, 2, 2>,
                         cudaFuncAttributeMaxDynamicSharedMemorySize, smem256);
    cudaFuncSetAttribute((const void*)attn64R_kernel,
                         cudaFuncAttributeMaxDynamicSharedMemorySize, smem64);
    cudaFuncSetAttribute((const void*)zzt2_kernel,
                         cudaFuncAttributeMaxDynamicSharedMemorySize, smemZZ);

    pack_adj_kernel<<<NN * NN / 256, 256>>>(adj, p_bits);

    // ---- layer 0 ----
    gemmtf_kernel<DIN><<<dim3(NN / 128, DH1 / 64), 256>>>(X, W0, p_h0, p_h0t, DH1);
    vals_kernel<<<NN / 8, 256>>>(p_h0, a0, DH1, p_rv, p_cv);
    attnR_kernel<DH1, 128, 2, 4, 2, 2><<<dim3(NN / 128, 2, 8), 256, smem256>>>(p_h0t, p_rv, p_cv, p_bits, p_pacc, p_pden);
    combine_kernel<<<NN * DH1 / 4 / 256, 256>>>(p_pacc, p_pden, p_hidden, DH1, 8);

    // ---- layers 1+2 fused ----
    gemmtf_kernel<DH1><<<dim3(NN / 128, 1), 256>>>(p_hidden, W1, p_h1, p_h1t, DH2);
    gemmtf_kernel<DH1><<<dim3(NN / 128, 1), 256>>>(p_hidden, W2, p_h2, p_h2t, DH2);
    vals_kernel<<<NN / 8, 256>>>(p_h1, a1, DH2, p_rv, p_cv);
    vals_kernel<<<NN / 8, 256>>>(p_h2, a2, DH2, p_rv2, p_cv2);
    attn64R_kernel<<<dim3(NN / 128, 2, 8), 256, smem64>>>(p_h1t, p_h2t, p_rv, p_cv, p_rv2, p_cv2, p_bits, p_pacc, p_pden);
    combine_z_kernel<<<NN * DH2 / 4 / 256, 256>>>(p_pacc, p_pden, noise, p_Z);

    // ---- decoder ----
    zzt2_kernel<<<dim3(NN / 128, NN / 128), 256, smemZZ>>>(p_Z, out);
}

// round 16
// speedup vs baseline: 1.6513x; 1.1079x over previous
#include <cuda_runtime.h>
#include <cuda_bf16.h>

#define NN 4096
#define DIN 512
#define DH1 256
#define DH2 64
#define ALPHA 0.2f

__device__ __forceinline__ unsigned f2tf(float f) {
    unsigned u; asm("cvt.rna.tf32.f32 %0, %1;" : "=r"(u) : "f"(f)); return u;
}
__device__ __forceinline__ void mma_tf32(float* c, const unsigned* a, unsigned b0, unsigned b1) {
    asm volatile("mma.sync.aligned.m16n8k8.row.col.f32.tf32.tf32.f32 "
                 "{%0,%1,%2,%3}, {%4,%5,%6,%7}, {%8,%9}, {%0,%1,%2,%3};"
                 : "+f"(c[0]), "+f"(c[1]), "+f"(c[2]), "+f"(c[3])
                 : "r"(a[0]), "r"(a[1]), "r"(a[2]), "r"(a[3]), "r"(b0), "r"(b1));
}
__device__ __forceinline__ void cp_async16(void* dst_smem, const void* src) {
    unsigned d = (unsigned)__cvta_generic_to_shared(dst_smem);
    asm volatile("cp.async.cg.shared.global [%0], [%1], 16;" :: "r"(d), "l"(src));
}
#define CP_COMMIT() asm volatile("cp.async.commit_group;")
#define CP_WAIT0()  asm volatile("cp.async.wait_group 0;")
#define CP_WAIT1()  asm volatile("cp.async.wait_group 1;")

// fma/alu-only exp2-based exp and sigmoid
__device__ __forceinline__ float fast_exp(float x) {
    float u = x * 1.44269504f;
    u = fminf(fmaxf(u, -60.f), 60.f);
    float s = u + 12582912.f;
    int n = __float_as_int(s) - 0x4B400000;
    float f = u - (s - 12582912.f);
    float p = 0.00133336f;
    p = fmaf(p, f, 0.00961813f);
    p = fmaf(p, f, 0.05550411f);
    p = fmaf(p, f, 0.24022651f);
    p = fmaf(p, f, 0.69314718f);
    p = fmaf(p, f, 1.0f);
    return __int_as_float(__float_as_int(p) + (n << 23));
}
__device__ __forceinline__ float fast_sigmoid(float x) {
    float e = fast_exp(-x);
    float d = 1.f + e;
    float y = __int_as_float(0x7EF311C3 - __float_as_int(d));
    y = y * fmaf(-d, y, 2.f);
    y = y * fmaf(-d, y, 2.f);
    return y;
}

// ---------------- device scratch (no allocations allowed) ----------------
__device__ float    g_h0[NN * DH1];
__device__ unsigned g_h0t[NN * DH1];
__device__ float    g_hidden[NN * DH1];
__device__ float    g_h1[NN * DH2];
__device__ unsigned g_h1t[NN * DH2];
__device__ float    g_h2[NN * DH2];
__device__ unsigned g_h2t[NN * DH2];
__device__ float    g_Z[NN * DH2];
__device__ float4   g_rowvals[NN];
__device__ float4   g_colvals[NN];
__device__ float4   g_rowvals2[NN];
__device__ float4   g_colvals2[NN];
__device__ unsigned g_adjbits[NN * (NN / 32)];
__device__ float    g_pacc[8 * NN * DH1];    // layer0: 8 splits x N x 256 (exact)
__device__ float    g_pden[16 * NN];

// ---------------- pack adjacency into bitmask ----------------------------
__global__ void pack_adj_kernel(const int* __restrict__ adj, unsigned* __restrict__ bits) {
    int idx = blockIdx.x * 256 + threadIdx.x;
    unsigned b = __ballot_sync(0xffffffffu, adj[idx] > 0);
    if ((threadIdx.x & 31) == 0) bits[idx >> 5] = b;
}

// ---------------- tf32 mma GEMM with dual (fp32 + tf32) output -----------
template<int K>
__global__ __launch_bounds__(256) void gemmtf_kernel(
    const float* __restrict__ A, const float* __restrict__ B,
    float* __restrict__ C, unsigned* __restrict__ Ct, int N)
{
    __shared__ __align__(16) unsigned As[128 * 36];
    __shared__ __align__(16) unsigned Bs[32 * 68];
    const int tid = threadIdx.x, wid = tid >> 5, lane = tid & 31;
    const int grp = lane >> 2, tid4 = lane & 3;
    const int warpRow = wid & 3, warpCol = wid >> 2;
    const int m0 = blockIdx.x * 128, n0 = blockIdx.y * 64;

    float acc[2][4][4] = {};
    for (int k0 = 0; k0 < K; k0 += 32) {
        __syncthreads();
#pragma unroll
        for (int it = 0; it < 4; ++it) {
            int q = tid + it * 256;
            int r = q >> 3, c4 = (q & 7) * 4;
            float4 v = *(const float4*)&A[(size_t)(m0 + r) * K + k0 + c4];
            uint4 t;
            t.x = f2tf(v.x); t.y = f2tf(v.y); t.z = f2tf(v.z); t.w = f2tf(v.w);
            *(uint4*)&As[r * 36 + c4] = t;
        }
#pragma unroll
        for (int it = 0; it < 2; ++it) {
            int q = tid + it * 256;
            int r = q >> 4, c4 = (q & 15) * 4;
            float4 v = *(const float4*)&B[(size_t)(k0 + r) * N + n0 + c4];
            uint4 t;
            t.x = f2tf(v.x); t.y = f2tf(v.y); t.z = f2tf(v.z); t.w = f2tf(v.w);
            *(uint4*)&Bs[r * 68 + c4] = t;
        }
        __syncthreads();
#pragma unroll
        for (int kk = 0; kk < 4; ++kk) {
            int kb = kk * 8;
            unsigned af[2][4];
#pragma unroll
            for (int m = 0; m < 2; ++m) {
                int rb = (warpRow * 2 + m) * 16;
                af[m][0] = As[(rb + grp) * 36 + kb + tid4];
                af[m][1] = As[(rb + grp + 8) * 36 + kb + tid4];
                af[m][2] = As[(rb + grp) * 36 + kb + tid4 + 4];
                af[m][3] = As[(rb + grp + 8) * 36 + kb + tid4 + 4];
            }
#pragma unroll
            for (int n = 0; n < 4; ++n) {
                int nn = warpCol * 32 + n * 8;
                unsigned b0 = Bs[(kb + tid4) * 68 + nn + grp];
                unsigned b1 = Bs[(kb + tid4 + 4) * 68 + nn + grp];
                mma_tf32(acc[0][n], af[0], b0, b1);
                mma_tf32(acc[1][n], af[1], b0, b1);
            }
        }
    }
#pragma unroll
    for (int m = 0; m < 2; ++m) {
        int r0 = m0 + (warpRow * 2 + m) * 16 + grp;
#pragma unroll
        for (int n = 0; n < 4; ++n) {
            int col = n0 + warpCol * 32 + n * 8 + 2 * tid4;
            float a0 = acc[m][n][0], a1 = acc[m][n][1];
            float a2 = acc[m][n][2], a3 = acc[m][n][3];
            *(float2*)&C[(size_t)r0 * N + col] = make_float2(a0, a1);
            *(float2*)&C[(size_t)(r0 + 8) * N + col] = make_float2(a2, a3);
            *(uint2*)&Ct[(size_t)r0 * N + col] = make_uint2(f2tf(a0), f2tf(a1));
            *(uint2*)&Ct[(size_t)(r0 + 8) * N + col] = make_uint2(f2tf(a2), f2tf(a3));
        }
    }
}

// ---- fused dual-weight N=64 GEMM: blockIdx.y selects (W1,h1)/(W2,h2) ----
__global__ __launch_bounds__(256) void gemmtf2_kernel(
    const float* __restrict__ A,
    const float* __restrict__ B1, const float* __restrict__ B2,
    float* __restrict__ C1, unsigned* __restrict__ Ct1,
    float* __restrict__ C2, unsigned* __restrict__ Ct2)
{
    constexpr int K = DH1, N = DH2;
    const float* B = blockIdx.y ? B2 : B1;
    float* C = blockIdx.y ? C2 : C1;
    unsigned* Ct = blockIdx.y ? Ct2 : Ct1;

    __shared__ __align__(16) unsigned As[128 * 36];
    __shared__ __align__(16) unsigned Bs[32 * 68];
    const int tid = threadIdx.x, wid = tid >> 5, lane = tid & 31;
    const int grp = lane >> 2, tid4 = lane & 3;
    const int warpRow = wid & 3, warpCol = wid >> 2;
    const int m0 = blockIdx.x * 128;

    float acc[2][4][4] = {};
    for (int k0 = 0; k0 < K; k0 += 32) {
        __syncthreads();
#pragma unroll
        for (int it = 0; it < 4; ++it) {
            int q = tid + it * 256;
            int r = q >> 3, c4 = (q & 7) * 4;
            float4 v = *(const float4*)&A[(size_t)(m0 + r) * K + k0 + c4];
            uint4 t;
            t.x = f2tf(v.x); t.y = f2tf(v.y); t.z = f2tf(v.z); t.w = f2tf(v.w);
            *(uint4*)&As[r * 36 + c4] = t;
        }
#pragma unroll
        for (int it = 0; it < 2; ++it) {
            int q = tid + it * 256;
            int r = q >> 4, c4 = (q & 15) * 4;
            float4 v = *(const float4*)&B[(size_t)(k0 + r) * N + c4];
            uint4 t;
            t.x = f2tf(v.x); t.y = f2tf(v.y); t.z = f2tf(v.z); t.w = f2tf(v.w);
            *(uint4*)&Bs[r * 68 + c4] = t;
        }
        __syncthreads();
#pragma unroll
        for (int kk = 0; kk < 4; ++kk) {
            int kb = kk * 8;
            unsigned af[2][4];
#pragma unroll
            for (int m = 0; m < 2; ++m) {
                int rb = (warpRow * 2 + m) * 16;
                af[m][0] = As[(rb + grp) * 36 + kb + tid4];
                af[m][1] = As[(rb + grp + 8) * 36 + kb + tid4];
                af[m][2] = As[(rb + grp) * 36 + kb + tid4 + 4];
                af[m][3] = As[(rb + grp + 8) * 36 + kb + tid4 + 4];
            }
#pragma unroll
            for (int n = 0; n < 4; ++n) {
                int nn = warpCol * 32 + n * 8;
                unsigned b0 = Bs[(kb + tid4) * 68 + nn + grp];
                unsigned b1 = Bs[(kb + tid4 + 4) * 68 + nn + grp];
                mma_tf32(acc[0][n], af[0], b0, b1);
                mma_tf32(acc[1][n], af[1], b0, b1);
            }
        }
    }
#pragma unroll
    for (int m = 0; m < 2; ++m) {
        int r0 = m0 + (warpRow * 2 + m) * 16 + grp;
#pragma unroll
        for (int n = 0; n < 4; ++n) {
            int col = warpCol * 32 + n * 8 + 2 * tid4;
            float a0 = acc[m][n][0], a1 = acc[m][n][1];
            float a2 = acc[m][n][2], a3 = acc[m][n][3];
            *(float2*)&C[(size_t)r0 * N + col] = make_float2(a0, a1);
            *(float2*)&C[(size_t)(r0 + 8) * N + col] = make_float2(a2, a3);
            *(uint2*)&Ct[(size_t)r0 * N + col] = make_uint2(f2tf(a0), f2tf(a1));
            *(uint2*)&Ct[(size_t)(r0 + 8) * N + col] = make_uint2(f2tf(a2), f2tf(a3));
        }
    }
}

// ---------------- per-row attention scalars ------------------------------
__global__ void vals_kernel(const float* __restrict__ h, const float* __restrict__ a,
                            int D, float4* __restrict__ rowvals, float4* __restrict__ colvals)
{
    int warp = (blockIdx.x * blockDim.x + threadIdx.x) >> 5;
    int lane = threadIdx.x & 31;
    if (warp >= NN) return;
    float s1 = 0.f, s2 = 0.f;
    for (int d = lane; d < D; d += 32) {
        float hv = h[(size_t)warp * D + d];
        s1 += hv * a[d];
        s2 += hv * a[D + d];
    }
#pragma unroll
    for (int o = 16; o; o >>= 1) {
        s1 += __shfl_xor_sync(0xffffffffu, s1, o);
        s2 += __shfl_xor_sync(0xffffffffu, s2, o);
    }
    if (lane == 0) {
        rowvals[warp] = make_float4(-s1, expf(s1), expf(ALPHA * s1), 0.f);
        colvals[warp] = make_float4(s2, expf(s2), expf(ALPHA * s2), 0.f);
    }
}

// fused D=64 vals for both layers: blockIdx.y selects layer
__global__ void vals2_kernel(const float* __restrict__ h1, const float* __restrict__ a1,
                             const float* __restrict__ h2, const float* __restrict__ a2,
                             float4* __restrict__ rv1, float4* __restrict__ cv1,
                             float4* __restrict__ rv2, float4* __restrict__ cv2)
{
    const float* h = blockIdx.y ? h2 : h1;
    const float* a = blockIdx.y ? a2 : a1;
    float4* rowvals = blockIdx.y ? rv2 : rv1;
    float4* colvals = blockIdx.y ? cv2 : cv1;
    int warp = (blockIdx.x * blockDim.x + threadIdx.x) >> 5;
    int lane = threadIdx.x & 31;
    if (warp >= NN) return;
    float s1 = 0.f, s2 = 0.f;
    for (int d = lane; d < DH2; d += 32) {
        float hv = h[(size_t)warp * DH2 + d];
        s1 += hv * a[d];
        s2 += hv * a[DH2 + d];
    }
#pragma unroll
    for (int o = 16; o; o >>= 1) {
        s1 += __shfl_xor_sync(0xffffffffu, s1, o);
        s2 += __shfl_xor_sync(0xffffffffu, s2, o);
    }
    if (lane == 0) {
        rowvals[warp] = make_float4(-s1, expf(s1), expf(ALPHA * s1), 0.f);
        colvals[warp] = make_float4(s2, expf(s2), expf(ALPHA * s2), 0.f);
    }
}

// ---------------- attention vR: weights-in-registers, 1 barrier/tile -----
template<int D, int DC, int MT, int ROWG, int COLG, int MAXB>
__global__ __launch_bounds__(256, MAXB) void attnR_kernel(
    const unsigned* __restrict__ ht,
    const float4* __restrict__ rowvals,
    const float4* __restrict__ colvals,
    const unsigned* __restrict__ adjbits,
    float* __restrict__ pacc,
    float* __restrict__ pden)
{
    constexpr int BI = 128, BJ = 32;
    constexpr int DCp = DC + 8;
    constexpr int NT = DC / (COLG * 8);
    constexpr int HS1 = BJ * DCp;
    constexpr int CP_IT = BJ * DC / (4 * 256);

    extern __shared__ __align__(16) unsigned smem_u[];
    unsigned* hs = smem_u;                         // [3][HS1]
    float4*   cvs = (float4*)(smem_u + 3 * HS1);   // [3][32]

    const int tid = threadIdx.x;
    const int wid = tid >> 5, lane = tid & 31;
    const int grp = lane >> 2, tid4 = lane & 3;
    const int warpRow = wid % ROWG, warpCol = wid / ROWG;
    const int rowbase = blockIdx.x * BI;
    const int colbase = blockIdx.y * DC;
    const int split = blockIdx.z;
    const int jcnt = NN / gridDim.z;
    const int jbeg = split * jcnt;
    const int T = jcnt / BJ;

    int ra[MT];
    float4 rva[MT], rvb[MT];
#pragma unroll
    for (int m = 0; m < MT; ++m) {
        ra[m] = rowbase + (warpRow * MT + m) * 16 + grp;
        rva[m] = rowvals[ra[m]];
        rvb[m] = rowvals[ra[m] + 8];
    }

    float acc[MT][NT][4];
#pragma unroll
    for (int m = 0; m < MT; ++m)
#pragma unroll
        for (int n = 0; n < NT; ++n)
#pragma unroll
            for (int q = 0; q < 4; ++q) acc[m][n][q] = 0.f;
    float denA[MT], denB[MT];
#pragma unroll
    for (int m = 0; m < MT; ++m) { denA[m] = 0.f; denB[m] = 0.f; }

    auto cp_tile = [&](int t, int buf) {
        const int j0 = jbeg + t * BJ;
        unsigned* hb = hs + buf * HS1;
#pragma unroll
        for (int it = 0; it < CP_IT; ++it) {
            int q = tid + it * 256;
            int row = q / (DC / 4);
            int c = (q % (DC / 4)) * 4;
            cp_async16(&hb[row * DCp + c], &ht[(size_t)(j0 + row) * D + colbase + c]);
        }
        if (tid < 32) cp_async16(&cvs[buf * 32 + tid], &colvals[j0 + tid]);
    };

    auto phase = [&](int buf, const unsigned* ma, const unsigned* mb) {
        const float4* cv = cvs + buf * 32;
        const unsigned* hb = hs + buf * HS1;
#pragma unroll
        for (int k0 = 0; k0 < BJ; k0 += 8) {
            const int j1 = k0 + tid4, j2 = j1 + 4;
            float4 c1 = cv[j1];
            float4 c2 = cv[j2];
            unsigned afr[MT][4];
#pragma unroll
            for (int m = 0; m < MT; ++m) {
                float w0 = (c1.x > rva[m].x) ? (rva[m].y * c1.y) : (rva[m].z * c1.z);
                float w1 = (c1.x > rvb[m].x) ? (rvb[m].y * c1.y) : (rvb[m].z * c1.z);
                float w2 = (c2.x > rva[m].x) ? (rva[m].y * c2.y) : (rva[m].z * c2.z);
                float w3 = (c2.x > rvb[m].x) ? (rvb[m].y * c2.y) : (rvb[m].z * c2.z);
                w0 = ((ma[m] >> j1) & 1u) ? w0 : 0.f;
                w1 = ((mb[m] >> j1) & 1u) ? w1 : 0.f;
                w2 = ((ma[m] >> j2) & 1u) ? w2 : 0.f;
                w3 = ((mb[m] >> j2) & 1u) ? w3 : 0.f;
                denA[m] += w0 + w2;
                denB[m] += w1 + w3;
                afr[m][0] = f2tf(w0); afr[m][1] = f2tf(w1);
                afr[m][2] = f2tf(w2); afr[m][3] = f2tf(w3);
            }
#pragma unroll
            for (int n = 0; n < NT; ++n) {
                int n0 = warpCol * (NT * 8) + n * 8;
                unsigned b0 = hb[(k0 + tid4) * DCp + n0 + grp];
                unsigned b1 = hb[(k0 + tid4 + 4) * DCp + n0 + grp];
#pragma unroll
                for (int m = 0; m < MT; ++m)
                    mma_tf32(acc[m][n], afr[m], b0, b1);
            }
        }
    };

    unsigned ma[MT], mb[MT], ma_n[MT], mb_n[MT];
    cp_tile(0, 0);
    CP_COMMIT();
    {
        const int w0 = jbeg >> 5;
#pragma unroll
        for (int m = 0; m < MT; ++m) {
            ma[m] = adjbits[(size_t)ra[m] * (NN / 32) + w0];
            mb[m] = adjbits[(size_t)(ra[m] + 8) * (NN / 32) + w0];
        }
    }

    for (int t = 0; t < T; ++t) {
        const bool more = (t + 1 < T);
        if (more) {
            cp_tile(t + 1, (t + 1) % 3);
            CP_COMMIT();
            const int wN = (jbeg + (t + 1) * BJ) >> 5;
#pragma unroll
            for (int m = 0; m < MT; ++m) {
                ma_n[m] = adjbits[(size_t)ra[m] * (NN / 32) + wN];
                mb_n[m] = adjbits[(size_t)(ra[m] + 8) * (NN / 32) + wN];
            }
            CP_WAIT1();
        } else {
            CP_WAIT0();
        }
        __syncthreads();
        phase(t % 3, ma, mb);
#pragma unroll
        for (int m = 0; m < MT; ++m) { ma[m] = ma_n[m]; mb[m] = mb_n[m]; }
    }

#pragma unroll
    for (int m = 0; m < MT; ++m) {
#pragma unroll
        for (int n = 0; n < NT; ++n) {
            int col = colbase + warpCol * (NT * 8) + n * 8 + 2 * tid4;
            float* p0 = pacc + ((size_t)split * NN + ra[m]) * D + col;
            float* p1 = pacc + ((size_t)split * NN + ra[m] + 8) * D + col;
            *(float2*)p0 = make_float2(acc[m][n][0], acc[m][n][1]);
            *(float2*)p1 = make_float2(acc[m][n][2], acc[m][n][3]);
        }
    }
    if (warpCol == 0 && blockIdx.y == 0) {
#pragma unroll
        for (int m = 0; m < MT; ++m) {
            float da = denA[m], db = denB[m];
            da += __shfl_xor_sync(0xffffffffu, da, 1);
            da += __shfl_xor_sync(0xffffffffu, da, 2);
            db += __shfl_xor_sync(0xffffffffu, db, 1);
            db += __shfl_xor_sync(0xffffffffu, db, 2);
            if (tid4 == 0) {
                pden[split * NN + ra[m]] = da;
                pden[split * NN + ra[m] + 8] = db;
            }
        }
    }
}

// ---------------- fused D=64 attention (register weights) ----------------
__global__ __launch_bounds__(256, 3) void attn64R_kernel(
    const unsigned* __restrict__ ht0, const unsigned* __restrict__ ht1,
    const float4* __restrict__ rv0, const float4* __restrict__ cv0,
    const float4* __restrict__ rv1, const float4* __restrict__ cv1,
    const unsigned* __restrict__ adjbits,
    float* __restrict__ pacc,
    float* __restrict__ pden)
{
    constexpr int BI = 128, BJ = 32, DC = 64, DCp = 72;
    constexpr int NT = 8;
    constexpr int HS1 = BJ * DCp;
    constexpr int CP_IT = 2;

    extern __shared__ __align__(16) unsigned smem_u[];
    unsigned* hs = smem_u;
    float4*   cvs = (float4*)(smem_u + 3 * HS1);

    const int tid = threadIdx.x;
    const int wid = tid >> 5, lane = tid & 31;
    const int grp = lane >> 2, tid4 = lane & 3;
    const int rowbase = blockIdx.x * BI;
    const int layer = blockIdx.y;
    const int split = blockIdx.z;
    const int jcnt = NN / gridDim.z;
    const int jbeg = split * jcnt;
    const int T = jcnt / BJ;

    const unsigned* ht = layer ? ht1 : ht0;
    const float4* rowvals = layer ? rv1 : rv0;
    const float4* colvals = layer ? cv1 : cv0;
    float* pacc_l = pacc + (size_t)layer * 8 * NN * DC;
    float* pden_l = pden + (size_t)layer * 8 * NN;

    const int ra = rowbase + wid * 16 + grp;
    const float4 rva = rowvals[ra];
    const float4 rvb = rowvals[ra + 8];

    float acc[NT][4];
#pragma unroll
    for (int n = 0; n < NT; ++n)
#pragma unroll
        for (int q = 0; q < 4; ++q) acc[n][q] = 0.f;
    float denA = 0.f, denB = 0.f;

    auto cp_tile = [&](int t, int buf) {
        const int j0 = jbeg + t * BJ;
        unsigned* hb = hs + buf * HS1;
#pragma unroll
        for (int it = 0; it < CP_IT; ++it) {
            int q = tid + it * 256;
            int row = q >> 4;
            int c = (q & 15) * 4;
            cp_async16(&hb[row * DCp + c], &ht[(size_t)(j0 + row) * DC + c]);
        }
        if (tid < 32) cp_async16(&cvs[buf * 32 + tid], &colvals[j0 + tid]);
    };

    auto phase = [&](int buf, unsigned ma, unsigned mb) {
        const float4* cv = cvs + buf * 32;
        const unsigned* hb = hs + buf * HS1;
#pragma unroll
        for (int k0 = 0; k0 < BJ; k0 += 8) {
            const int j1 = k0 + tid4, j2 = j1 + 4;
            float4 c1 = cv[j1];
            float4 c2 = cv[j2];
            float w0 = (c1.x > rva.x) ? (rva.y * c1.y) : (rva.z * c1.z);
            float w1 = (c1.x > rvb.x) ? (rvb.y * c1.y) : (rvb.z * c1.z);
            float w2 = (c2.x > rva.x) ? (rva.y * c2.y) : (rva.z * c2.z);
            float w3 = (c2.x > rvb.x) ? (rvb.y * c2.y) : (rvb.z * c2.z);
            w0 = ((ma >> j1) & 1u) ? w0 : 0.f;
            w1 = ((mb >> j1) & 1u) ? w1 : 0.f;
            w2 = ((ma >> j2) & 1u) ? w2 : 0.f;
            w3 = ((mb >> j2) & 1u) ? w3 : 0.f;
            denA += w0 + w2;
            denB += w1 + w3;
            unsigned afr[4];
            afr[0] = f2tf(w0); afr[1] = f2tf(w1);
            afr[2] = f2tf(w2); afr[3] = f2tf(w3);
#pragma unroll
            for (int n = 0; n < NT; ++n) {
                int n0 = n * 8;
                unsigned b0 = hb[(k0 + tid4) * DCp + n0 + grp];
                unsigned b1 = hb[(k0 + tid4 + 4) * DCp + n0 + grp];
                mma_tf32(acc[n], afr, b0, b1);
            }
        }
    };

    unsigned ma, mb, ma_n = 0, mb_n = 0;
    cp_tile(0, 0);
    CP_COMMIT();
    {
        const int w0 = jbeg >> 5;
        ma = adjbits[(size_t)ra * (NN / 32) + w0];
        mb = adjbits[(size_t)(ra + 8) * (NN / 32) + w0];
    }

    for (int t = 0; t < T; ++t) {
        const bool more = (t + 1 < T);
        if (more) {
            cp_tile(t + 1, (t + 1) % 3);
            CP_COMMIT();
            const int wN = (jbeg + (t + 1) * BJ) >> 5;
            ma_n = adjbits[(size_t)ra * (NN / 32) + wN];
            mb_n = adjbits[(size_t)(ra + 8) * (NN / 32) + wN];
            CP_WAIT1();
        } else {
            CP_WAIT0();
        }
        __syncthreads();
        phase(t % 3, ma, mb);
        ma = ma_n; mb = mb_n;
    }

#pragma unroll
    for (int n = 0; n < NT; ++n) {
        int col = n * 8 + 2 * tid4;
        float* p0 = pacc_l + ((size_t)split * NN + ra) * DC + col;
        float* p1 = pacc_l + ((size_t)split * NN + ra + 8) * DC + col;
        *(float2*)p0 = make_float2(acc[n][0], acc[n][1]);
        *(float2*)p1 = make_float2(acc[n][2], acc[n][3]);
    }
    {
        float da = denA, db = denB;
        da += __shfl_xor_sync(0xffffffffu, da, 1);
        da += __shfl_xor_sync(0xffffffffu, da, 2);
        db += __shfl_xor_sync(0xffffffffu, db, 1);
        db += __shfl_xor_sync(0xffffffffu, db, 2);
        if (tid4 == 0) {
            pden_l[split * NN + ra] = da;
            pden_l[split * NN + ra + 8] = db;
        }
    }
}

// ---------------- combine split partials + normalize (layer 0) -----------
__global__ void combine_kernel(const float* __restrict__ pacc, const float* __restrict__ pden,
                               float* __restrict__ out, int D, int nsplit)
{
    int idx = blockIdx.x * blockDim.x + threadIdx.x;
    int total = NN * D / 4;
    if (idx >= total) return;
    int row = idx / (D / 4);
    float4 s = make_float4(0.f, 0.f, 0.f, 0.f);
    float dd = 0.f;
    for (int sp = 0; sp < nsplit; ++sp) {
        float4 v = ((const float4*)pacc)[(size_t)sp * total + idx];
        s.x += v.x; s.y += v.y; s.z += v.z; s.w += v.w;
        dd += pden[sp * NN + row];
    }
    float inv = 1.f / dd;
    s.x *= inv; s.y *= inv; s.z *= inv; s.w *= inv;
    ((float4*)out)[idx] = s;
}

// ---------------- combine both D=64 layers + Z in one pass ---------------
__global__ void combine_z_kernel(const float* __restrict__ pacc, const float* __restrict__ pden,
                                 const float* __restrict__ noise, float* __restrict__ Z)
{
    int idx = blockIdx.x * blockDim.x + threadIdx.x;
    const int total = NN * DH2 / 4;
    if (idx >= total) return;
    int row = idx / (DH2 / 4);
    const float4* pm = (const float4*)pacc;
    const float4* pl = (const float4*)(pacc + (size_t)8 * NN * DH2);
    float4 m = make_float4(0.f, 0.f, 0.f, 0.f);
    float4 l = make_float4(0.f, 0.f, 0.f, 0.f);
    float dm = 0.f, dl = 0.f;
    for (int sp = 0; sp < 8; ++sp) {
        float4 v = pm[(size_t)sp * total + idx];
        m.x += v.x; m.y += v.y; m.z += v.z; m.w += v.w;
        float4 u = pl[(size_t)sp * total + idx];
        l.x += u.x; l.y += u.y; l.z += u.z; l.w += u.w;
        dm += pden[sp * NN + row];
        dl += pden[8 * NN + sp * NN + row];
    }
    float im = 1.f / dm, il = 1.f / dl;
    float4 nz = ((const float4*)noise)[idx];
    float4 z;
    z.x = nz.x * fast_exp(l.x * il) + m.x * im;
    z.y = nz.y * fast_exp(l.y * il) + m.y * im;
    z.z = nz.z * fast_exp(l.z * il) + m.z * im;
    z.w = nz.w * fast_exp(l.w * il) + m.w * im;
    ((float4*)Z)[idx] = z;
}

// ---------------- A = sigmoid(Z @ Z^T): tf32 mma, coalesced mirror -------
__global__ __launch_bounds__(256, 2) void zzt2_kernel(const float* __restrict__ Z,
                                                      float* __restrict__ out)
{
    const int bi = blockIdx.y, bj = blockIdx.x;
    if (bj < bi) return;
    extern __shared__ __align__(16) unsigned zs[];
    unsigned* Zi = zs;
    unsigned* Zj = zs + 128 * 68;
    const int tid = threadIdx.x, wid = tid >> 5, lane = tid & 31;
    const int grp = lane >> 2, tid4 = lane & 3;
    const int warpRow = wid & 3, warpCol = wid >> 2;
    const int i0 = bi * 128, j0 = bj * 128;

#pragma unroll
    for (int it = 0; it < 16; ++it) {
        int q = tid + it * 256;
        int tile = q >> 11;
        int qq = q & 2047;
        int r = qq >> 4, c4 = (qq & 15) * 4;
        int gr = (tile ? j0 : i0) + r;
        float4 v = *(const float4*)&Z[(size_t)gr * DH2 + c4];
        uint4 t;
        t.x = f2tf(v.x); t.y = f2tf(v.y); t.z = f2tf(v.z); t.w = f2tf(v.w);
        *(uint4*)&((tile ? Zj : Zi)[r * 68 + c4]) = t;
    }
    __syncthreads();

    float acc[2][8][4] = {};
#pragma unroll
    for (int kk = 0; kk < 8; ++kk) {
        int kb = kk * 8;
        unsigned af[2][4];
#pragma unroll
        for (int m = 0; m < 2; ++m) {
            int rb = (warpRow * 2 + m) * 16;
            af[m][0] = Zi[(rb + grp) * 68 + kb + tid4];
            af[m][1] = Zi[(rb + grp + 8) * 68 + kb + tid4];
            af[m][2] = Zi[(rb + grp) * 68 + kb + tid4 + 4];
            af[m][3] = Zi[(rb + grp + 8) * 68 + kb + tid4 + 4];
        }
#pragma unroll
        for (int n = 0; n < 8; ++n) {
            int nn = warpCol * 64 + n * 8;
            unsigned b0 = Zj[(nn + grp) * 68 + kb + tid4];
            unsigned b1 = Zj[(nn + grp) * 68 + kb + tid4 + 4];
#pragma unroll
            for (int m = 0; m < 2; ++m)
                mma_tf32(acc[m][n], af[m], b0, b1);
        }
    }

#pragma unroll
    for (int m = 0; m < 2; ++m) {
        int r0 = i0 + (warpRow * 2 + m) * 16 + grp;
#pragma unroll
        for (int n = 0; n < 8; ++n) {
            int col = j0 + warpCol * 64 + n * 8 + 2 * tid4;
#pragma unroll
            for (int q = 0; q < 4; ++q) acc[m][n][q] = fast_sigmoid(acc[m][n][q]);
            *(float2*)&out[(size_t)r0 * NN + col] = make_float2(acc[m][n][0], acc[m][n][1]);
            *(float2*)&out[(size_t)(r0 + 8) * NN + col] = make_float2(acc[m][n][2], acc[m][n][3]);
        }
    }

    if (bj > bi) {
        __syncthreads();
        float* sT = (float*)zs;
#pragma unroll
        for (int m = 0; m < 2; ++m) {
            int lr0 = (warpRow * 2 + m) * 16 + grp;
#pragma unroll
            for (int n = 0; n < 8; ++n) {
                int lc = warpCol * 64 + n * 8 + 2 * tid4;
                sT[(size_t)lc * 132 + lr0] = acc[m][n][0];
                sT[(size_t)(lc + 1) * 132 + lr0] = acc[m][n][1];
                sT[(size_t)lc * 132 + lr0 + 8] = acc[m][n][2];
                sT[(size_t)(lc + 1) * 132 + lr0 + 8] = acc[m][n][3];
            }
        }
        __syncthreads();
#pragma unroll
        for (int it = 0; it < 16; ++it) {
            int q = tid + it * 256;
            int rr = q >> 5, cc = (q & 31) * 4;
            float4 v = *(float4*)&sT[(size_t)rr * 132 + cc];
            *(float4*)&out[(size_t)(j0 + rr) * NN + i0 + cc] = v;
        }
    }
}

// ---------------- host orchestration -------------------------------------
extern "C" void kernel_launch(void* const* d_in, const int* in_sizes, int n_in,
                              void* d_out, int out_size)
{
    const float* X     = (const float*)d_in[0];
    const int*   adj   = (const int*)  d_in[1];
    const float* noise = (const float*)d_in[2];
    const float* W0    = (const float*)d_in[3];
    const float* a0    = (const float*)d_in[4];
    const float* W1    = (const float*)d_in[5];
    const float* a1    = (const float*)d_in[6];
    const float* W2    = (const float*)d_in[7];
    const float* a2    = (const float*)d_in[8];
    float* out = (float*)d_out;

    float *p_h0, *p_hidden, *p_h1, *p_h2, *p_Z, *p_pacc, *p_pden;
    unsigned *p_h0t, *p_h1t, *p_h2t;
    float4 *p_rv, *p_cv, *p_rv2, *p_cv2;
    unsigned* p_bits;
    cudaGetSymbolAddress((void**)&p_h0, g_h0);
    cudaGetSymbolAddress((void**)&p_h0t, g_h0t);
    cudaGetSymbolAddress((void**)&p_hidden, g_hidden);
    cudaGetSymbolAddress((void**)&p_h1, g_h1);
    cudaGetSymbolAddress((void**)&p_h1t, g_h1t);
    cudaGetSymbolAddress((void**)&p_h2, g_h2);
    cudaGetSymbolAddress((void**)&p_h2t, g_h2t);
    cudaGetSymbolAddress((void**)&p_Z, g_Z);
    cudaGetSymbolAddress((void**)&p_pacc, g_pacc);
    cudaGetSymbolAddress((void**)&p_pden, g_pden);
    cudaGetSymbolAddress((void**)&p_rv, g_rowvals);
    cudaGetSymbolAddress((void**)&p_cv, g_colvals);
    cudaGetSymbolAddress((void**)&p_rv2, g_rowvals2);
    cudaGetSymbolAddress((void**)&p_cv2, g_colvals2);
    cudaGetSymbolAddress((void**)&p_bits, g_adjbits);

    const int smem256 = (3 * 32 * 136) * 4 + 3 * 32 * 16;   // 53760
    const int smem64  = (3 * 32 * 72) * 4 + 3 * 32 * 16;    // 29184
    const int smemZZ  = 2 * 128 * 68 * 4;                   // 69632
    cudaFuncSetAttribute((const void*)attnR_kernel<DH1, 128, 1, 8, 1, 2>,
                         cudaFuncAttributeMaxDynamicSharedMemorySize, smem256);
    cudaFuncSetAttribute((const void*)attn64R_kernel,
                         cudaFuncAttributeMaxDynamicSharedMemorySize, smem64);
    cudaFuncSetAttribute((const void*)zzt2_kernel,
                         cudaFuncAttributeMaxDynamicSharedMemorySize, smemZZ);

    pack_adj_kernel<<<NN * NN / 256, 256>>>(adj, p_bits);

    // ---- layer 0 ----
    gemmtf_kernel<DIN><<<dim3(NN / 128, DH1 / 64), 256>>>(X, W0, p_h0, p_h0t, DH1);
    vals_kernel<<<NN / 8, 256>>>(p_h0, a0, DH1, p_rv, p_cv);
    attnR_kernel<DH1, 128, 1, 8, 1, 2><<<dim3(NN / 128, 2, 8), 256, smem256>>>(p_h0t, p_rv, p_cv, p_bits, p_pacc, p_pden);
    combine_kernel<<<NN * DH1 / 4 / 256, 256>>>(p_pacc, p_pden, p_hidden, DH1, 8);

    // ---- layers 1+2 fused ----
    gemmtf2_kernel<<<dim3(NN / 128, 2), 256>>>(p_hidden, W1, W2, p_h1, p_h1t, p_h2, p_h2t);
    vals2_kernel<<<dim3(NN / 8, 2), 256>>>(p_h1, a1, p_h2, a2, p_rv, p_cv, p_rv2, p_cv2);
    attn64R_kernel<<<dim3(NN / 128, 2, 8), 256, smem64>>>(p_h1t, p_h2t, p_rv, p_cv, p_rv2, p_cv2, p_bits, p_pacc, p_pden);
    combine_z_kernel<<<NN * DH2 / 4 / 256, 256>>>(p_pacc, p_pden, noise, p_Z);

    // ---- decoder ----
    zzt2_kernel<<<dim3(NN / 128, NN / 128), 256, smemZZ>>>(p_Z, out);
}